// round 1
// baseline (speedup 1.0000x reference)
#include <cuda_runtime.h>
#include <cuda_bf16.h>
#include <math.h>

// ---------------------------------------------------------------------------
// Problem constants
// ---------------------------------------------------------------------------
#define S_   256
#define LA_  128
#define LB_  512
#define DQ_  256
#define DKV_ 265
#define DQK_ 512
#define DV_  512

#define ROWS_A (S_ * LA_)   // 32768
#define ROWS_B (S_ * LB_)   // 131072

// Scratch (device globals; no allocation allowed)
__device__ float g_Yq [(size_t)ROWS_A * DQK_];   //  64 MB
__device__ float g_Yk [(size_t)ROWS_B * DQK_];   // 256 MB
__device__ float g_Yv [(size_t)ROWS_B * DV_];    // 256 MB
__device__ float g_Ywv[(size_t)ROWS_A * DV_];    //  64 MB
__device__ float g_Yf [(size_t)ROWS_A * DQ_];    //  32 MB
__device__ float g_stats[8 * 512];               // [q_sum,q_sq,k_sum,k_sq,v_sum,v_sq,f_sum,f_sq]
__device__ float g_cnt[2];                       // cnt_a, cnt_b

// ---------------------------------------------------------------------------
// Small init kernels
// ---------------------------------------------------------------------------
__global__ void zero_stats_kernel() {
    int i = blockIdx.x * blockDim.x + threadIdx.x;
    if (i < 8 * 512) g_stats[i] = 0.0f;
}

__global__ void cnt_kernel(const int* __restrict__ a_lens,
                           const int* __restrict__ b_lens) {
    __shared__ int sh[256];
    int t = threadIdx.x;
    sh[t] = a_lens[t];
    __syncthreads();
    for (int o = 128; o; o >>= 1) { if (t < o) sh[t] += sh[t + o]; __syncthreads(); }
    if (t == 0) g_cnt[0] = (float)sh[0];
    __syncthreads();
    sh[t] = b_lens[t];
    __syncthreads();
    for (int o = 128; o; o >>= 1) { if (t < o) sh[t] += sh[t + o]; __syncthreads(); }
    if (t == 0) g_cnt[1] = (float)sh[0];
}

// ---------------------------------------------------------------------------
// Generic fp32 GEMM:  C[M,N] = X[M,K] @ W[N,K]^T + bias
// 64x64 tile, BK=16, 256 threads, 4x4 per-thread micro-tile.
// ---------------------------------------------------------------------------
#define GBM 64
#define GBN 64
#define GBK 16
#define GPAD 1

__global__ __launch_bounds__(256)
void gemm_nt(const float* __restrict__ X, const float* __restrict__ W,
             const float* __restrict__ bias, float* __restrict__ C,
             int M, int N, int K) {
    __shared__ float Xs[GBK][GBM + GPAD];
    __shared__ float Ws[GBK][GBN + GPAD];

    int tid  = threadIdx.x;
    int row0 = blockIdx.y * GBM;
    int col0 = blockIdx.x * GBN;
    int tr   = tid >> 4;        // 0..15
    int tc   = tid & 15;        // 0..15

    float acc[4][4];
#pragma unroll
    for (int i = 0; i < 4; i++)
#pragma unroll
        for (int j = 0; j < 4; j++) acc[i][j] = 0.0f;

    for (int k0 = 0; k0 < K; k0 += GBK) {
#pragma unroll
        for (int i = 0; i < 4; i++) {
            int idx = tid + i * 256;          // 0..1023
            int r   = idx >> 4;               // 0..63
            int kk  = idx & 15;               // 0..15
            int gk  = k0 + kk;

            float xv = 0.0f;
            int gr = row0 + r;
            if (gr < M && gk < K) xv = X[(size_t)gr * K + gk];
            Xs[kk][r] = xv;

            float wv = 0.0f;
            int gc = col0 + r;
            if (gc < N && gk < K) wv = W[(size_t)gc * K + gk];
            Ws[kk][r] = wv;
        }
        __syncthreads();

#pragma unroll
        for (int kk = 0; kk < GBK; kk++) {
            float xr[4], wr[4];
#pragma unroll
            for (int i = 0; i < 4; i++) xr[i] = Xs[kk][tr * 4 + i];
#pragma unroll
            for (int j = 0; j < 4; j++) wr[j] = Ws[kk][tc * 4 + j];
#pragma unroll
            for (int i = 0; i < 4; i++)
#pragma unroll
                for (int j = 0; j < 4; j++)
                    acc[i][j] = fmaf(xr[i], wr[j], acc[i][j]);
        }
        __syncthreads();
    }

#pragma unroll
    for (int i = 0; i < 4; i++) {
        int gr = row0 + tr * 4 + i;
        if (gr >= M) continue;
#pragma unroll
        for (int j = 0; j < 4; j++) {
            int gc = col0 + tc * 4 + j;
            if (gc < N) C[(size_t)gr * N + gc] = acc[i][j] + bias[gc];
        }
    }
}

// ---------------------------------------------------------------------------
// Masked per-channel sum / sumsq over rows.  Row r valid iff (r%L) < lens[r/L].
// Each block reduces a stripe of rows; per-thread channel accumulators;
// atomicAdd of per-block partials (few hundred per address -> cheap).
// ---------------------------------------------------------------------------
__global__ __launch_bounds__(256)
void stats_kernel(const float* __restrict__ Y, const int* __restrict__ lens,
                  int L, int nRows, int D, int rowsPerBlock,
                  float* __restrict__ sumOut, float* __restrict__ sqOut) {
    int r0 = blockIdx.x * rowsPerBlock;
    int r1 = min(r0 + rowsPerBlock, nRows);
    int c0 = threadIdx.x;
    int c1 = threadIdx.x + 256;

    float s0 = 0.f, q0 = 0.f, s1 = 0.f, q1 = 0.f;
    for (int r = r0; r < r1; r++) {
        int sidx = r / L;
        int l    = r - sidx * L;
        if (l >= lens[sidx]) continue;
        const float* row = Y + (size_t)r * D;
        float v = row[c0]; s0 += v; q0 += v * v;
        if (c1 < D) { float w = row[c1]; s1 += w; q1 += w * w; }
    }
    atomicAdd(&sumOut[c0], s0);
    atomicAdd(&sqOut[c0],  q0);
    if (c1 < D) {
        atomicAdd(&sumOut[c1], s1);
        atomicAdd(&sqOut[c1],  q1);
    }
}

// ---------------------------------------------------------------------------
// BN (from accumulated stats) + ReLU + optional L2 row-normalize + optional
// output row-masking.  One block (128 threads) per row.
// ---------------------------------------------------------------------------
__global__ __launch_bounds__(128)
void bn_apply_kernel(float* __restrict__ Y, int D,
                     const float* __restrict__ ssum, const float* __restrict__ ssq,
                     const float* __restrict__ cntp,
                     const float* __restrict__ gamma, const float* __restrict__ beta,
                     const int* __restrict__ lens, int L,
                     int normalize, int maskOut, float* __restrict__ out) {
    int r = blockIdx.x;
    int sidx = r / L;
    int l    = r - sidx * L;
    bool valid = (l < lens[sidx]);

    float inv = 1.0f / (*cntp);
    int t = threadIdx.x;
    int per = D >> 7;          // D/128 : 4 for 512, 2 for 256

    float vals[4];
    float ss = 0.0f;
#pragma unroll 4
    for (int i = 0; i < per; i++) {
        int c = t + (i << 7);
        float mean = ssum[c] * inv;
        float var  = ssq[c] * inv - mean * mean;
        var = fmaxf(var, 0.0f);
        float z = (Y[(size_t)r * D + c] - mean) * rsqrtf(var + 1e-5f) * gamma[c] + beta[c];
        z = fmaxf(z, 0.0f);
        vals[i] = z;
        ss += z * z;
    }

    __shared__ float red[4];
#pragma unroll
    for (int o = 16; o; o >>= 1) ss += __shfl_xor_sync(0xffffffffu, ss, o);
    if ((t & 31) == 0) red[t >> 5] = ss;
    __syncthreads();
    float tot = red[0] + red[1] + red[2] + red[3];

    float scale = 1.0f;
    if (normalize) scale = 1.0f / fmaxf(sqrtf(tot), 1e-12f);
    if (maskOut && !valid) scale = 0.0f;

    float* dst = out ? out : Y;
#pragma unroll 4
    for (int i = 0; i < per; i++) {
        int c = t + (i << 7);
        dst[(size_t)r * D + c] = vals[i] * scale;
    }
}

// ---------------------------------------------------------------------------
// Attention: per block (s, 16-row q tile).  256 threads, 4x8 micro-tiles.
//  Phase A: scores[16][512] = Q_tile @ K^T  (K staged transposed in smem)
//  softmax (warp per 2 rows), masked to -1e30 for b >= b_lens[s]
//  Phase B: wv[16][512] = W @ V            (V streamed through smem)
// Dynamic smem: scores 16*512 | buf 32*513 | Q 16*33  -> 100544 B
// ---------------------------------------------------------------------------
#define KS_STRIDE 513
#define ATT_SMEM_FLOATS (16 * 512 + 32 * KS_STRIDE + 16 * 33)
#define ATT_SMEM_BYTES  (ATT_SMEM_FLOATS * 4)

__global__ __launch_bounds__(256)
void attention_kernel(const float* __restrict__ q, const float* __restrict__ k,
                      const float* __restrict__ v, const int* __restrict__ b_lens,
                      float* __restrict__ wv) {
    extern __shared__ float smem[];
    float* sS   = smem;                       // [16][512]
    float* sBuf = smem + 16 * 512;            // [32][513] (K^T) / [32][512] (V)
    float* sQ   = sBuf + 32 * KS_STRIDE;      // [16][33]

    int s   = blockIdx.x;
    int a0  = blockIdx.y * 16;
    int tid = threadIdx.x;
    int ty  = tid >> 6;       // 0..3   -> a rows ty*4..ty*4+3
    int tx  = tid & 63;       // 0..63  -> cols tx + 64*j
    int nb  = b_lens[s];

    const float* qs = q + ((size_t)s * LA_ + a0) * DQK_;
    const float* ks = k + (size_t)s * LB_ * DQK_;
    const float* vs = v + (size_t)s * LB_ * DV_;

    float acc[4][8];
#pragma unroll
    for (int i = 0; i < 4; i++)
#pragma unroll
        for (int j = 0; j < 8; j++) acc[i][j] = 0.0f;

    // ---------------- Phase A: scores = Q K^T ----------------
    for (int d0 = 0; d0 < DQK_; d0 += 32) {
        {   // Q tile: 16 x 32
            int idx = tid * 2;
            int r = idx >> 5, kk = idx & 31;
            sQ[r * 33 + kk]     = qs[r * DQK_ + d0 + kk];
            sQ[r * 33 + kk + 1] = qs[r * DQK_ + d0 + kk + 1];
        }
        // K tile transposed: 512 b-rows x 8 float4 each
#pragma unroll
        for (int i = 0; i < 16; i++) {
            int idx = tid + 256 * i;
            int b = idx >> 3, f4 = idx & 7;
            float4 kv = *reinterpret_cast<const float4*>(ks + (size_t)b * DQK_ + d0 + f4 * 4);
            sBuf[(f4 * 4 + 0) * KS_STRIDE + b] = kv.x;
            sBuf[(f4 * 4 + 1) * KS_STRIDE + b] = kv.y;
            sBuf[(f4 * 4 + 2) * KS_STRIDE + b] = kv.z;
            sBuf[(f4 * 4 + 3) * KS_STRIDE + b] = kv.w;
        }
        __syncthreads();

#pragma unroll
        for (int kk = 0; kk < 32; kk++) {
            float qr[4], kr[8];
#pragma unroll
            for (int i = 0; i < 4; i++) qr[i] = sQ[(ty * 4 + i) * 33 + kk];
#pragma unroll
            for (int j = 0; j < 8; j++) kr[j] = sBuf[kk * KS_STRIDE + tx + 64 * j];
#pragma unroll
            for (int i = 0; i < 4; i++)
#pragma unroll
                for (int j = 0; j < 8; j++)
                    acc[i][j] = fmaf(qr[i], kr[j], acc[i][j]);
        }
        __syncthreads();
    }

    // scale + mask -> smem
    const float scaler = 6.25f;    // 1 / (0.01 * sqrt(256))
#pragma unroll
    for (int i = 0; i < 4; i++)
#pragma unroll
        for (int j = 0; j < 8; j++) {
            int b = tx + 64 * j;
            float val = acc[i][j] * scaler;
            if (b >= nb) val = -1e30f;
            sS[(ty * 4 + i) * 512 + b] = val;
        }
    __syncthreads();

    // ---------------- softmax: warp per 2 rows ----------------
    {
        int w = tid >> 5, lane = tid & 31;
#pragma unroll
        for (int rr = 0; rr < 2; rr++) {
            int row = w * 2 + rr;
            float m = -1e30f;
            for (int c = lane; c < 512; c += 32) m = fmaxf(m, sS[row * 512 + c]);
#pragma unroll
            for (int o = 16; o; o >>= 1) m = fmaxf(m, __shfl_xor_sync(0xffffffffu, m, o));
            float sum = 0.0f;
            for (int c = lane; c < 512; c += 32) {
                float e = expf(sS[row * 512 + c] - m);
                sS[row * 512 + c] = e;
                sum += e;
            }
#pragma unroll
            for (int o = 16; o; o >>= 1) sum += __shfl_xor_sync(0xffffffffu, sum, o);
            float invs = 1.0f / sum;
            for (int c = lane; c < 512; c += 32) sS[row * 512 + c] *= invs;
        }
    }
    __syncthreads();

    // ---------------- Phase B: wv = W V ----------------
#pragma unroll
    for (int i = 0; i < 4; i++)
#pragma unroll
        for (int j = 0; j < 8; j++) acc[i][j] = 0.0f;

    for (int b0 = 0; b0 < LB_; b0 += 32) {
#pragma unroll
        for (int i = 0; i < 16; i++) {
            int idx = tid + 256 * i;
            int kk = idx >> 7, f4 = idx & 127;
            float4 vv = *reinterpret_cast<const float4*>(vs + (size_t)(b0 + kk) * DV_ + f4 * 4);
            *reinterpret_cast<float4*>(&sBuf[kk * 512 + f4 * 4]) = vv;
        }
        __syncthreads();

#pragma unroll
        for (int kk = 0; kk < 32; kk++) {
            float wr[4], vr[8];
#pragma unroll
            for (int i = 0; i < 4; i++) wr[i] = sS[(ty * 4 + i) * 512 + b0 + kk];
#pragma unroll
            for (int j = 0; j < 8; j++) vr[j] = sBuf[kk * 512 + tx + 64 * j];
#pragma unroll
            for (int i = 0; i < 4; i++)
#pragma unroll
                for (int j = 0; j < 8; j++)
                    acc[i][j] = fmaf(wr[i], vr[j], acc[i][j]);
        }
        __syncthreads();
    }

    float* wvp = wv + ((size_t)s * LA_ + a0) * DV_;
#pragma unroll
    for (int i = 0; i < 4; i++)
#pragma unroll
        for (int j = 0; j < 8; j++)
            wvp[(ty * 4 + i) * DV_ + tx + 64 * j] = acc[i][j];
}

// ---------------------------------------------------------------------------
// Launch
// ---------------------------------------------------------------------------
extern "C" void kernel_launch(void* const* d_in, const int* in_sizes, int n_in,
                              void* d_out, int out_size) {
    const float* A      = (const float*)d_in[0];
    const float* B      = (const float*)d_in[1];
    const int*   a_lens = (const int*)  d_in[2];
    const int*   b_lens = (const int*)  d_in[3];
    const float* Wq     = (const float*)d_in[4];
    const float* bq     = (const float*)d_in[5];
    const float* gq     = (const float*)d_in[6];
    const float* betaq  = (const float*)d_in[7];
    const float* Wk     = (const float*)d_in[8];
    const float* bk     = (const float*)d_in[9];
    const float* gk     = (const float*)d_in[10];
    const float* betak  = (const float*)d_in[11];
    const float* Wv     = (const float*)d_in[12];
    const float* bv     = (const float*)d_in[13];
    const float* gv     = (const float*)d_in[14];
    const float* betav  = (const float*)d_in[15];
    const float* Wf     = (const float*)d_in[16];
    const float* bf     = (const float*)d_in[17];
    const float* gf     = (const float*)d_in[18];
    const float* betaf  = (const float*)d_in[19];
    float* out = (float*)d_out;

    float *Yq, *Yk, *Yv, *Ywv, *Yf, *stats, *cnt;
    cudaGetSymbolAddress((void**)&Yq,   g_Yq);
    cudaGetSymbolAddress((void**)&Yk,   g_Yk);
    cudaGetSymbolAddress((void**)&Yv,   g_Yv);
    cudaGetSymbolAddress((void**)&Ywv,  g_Ywv);
    cudaGetSymbolAddress((void**)&Yf,   g_Yf);
    cudaGetSymbolAddress((void**)&stats, g_stats);
    cudaGetSymbolAddress((void**)&cnt,  g_cnt);

    cudaFuncSetAttribute(attention_kernel,
                         cudaFuncAttributeMaxDynamicSharedMemorySize, ATT_SMEM_BYTES);

    float* sum_q = stats + 0 * 512;
    float* sq_q  = stats + 1 * 512;
    float* sum_k = stats + 2 * 512;
    float* sq_k  = stats + 3 * 512;
    float* sum_v = stats + 4 * 512;
    float* sq_v  = stats + 5 * 512;
    float* sum_f = stats + 6 * 512;
    float* sq_f  = stats + 7 * 512;

    // 0) reset accumulators (part of the graph: runs on every replay)
    zero_stats_kernel<<<16, 256>>>();
    cnt_kernel<<<1, 256>>>(a_lens, b_lens);

    // 1) projection GEMMs
    gemm_nt<<<dim3(DQK_ / GBN, ROWS_A / GBM), 256>>>(A, Wq, bq, Yq, ROWS_A, DQK_, DQ_);
    gemm_nt<<<dim3(DQK_ / GBN, ROWS_B / GBM), 256>>>(B, Wk, bk, Yk, ROWS_B, DQK_, DKV_);
    gemm_nt<<<dim3(DV_  / GBN, ROWS_B / GBM), 256>>>(B, Wv, bv, Yv, ROWS_B, DV_,  DKV_);

    // 2) masked BN stats
    stats_kernel<<<128, 256>>>(Yq, a_lens, LA_, ROWS_A, DQK_, 256, sum_q, sq_q);
    stats_kernel<<<512, 256>>>(Yk, b_lens, LB_, ROWS_B, DQK_, 256, sum_k, sq_k);
    stats_kernel<<<512, 256>>>(Yv, b_lens, LB_, ROWS_B, DV_,  256, sum_v, sq_v);

    // 3) BN + ReLU + L2-normalize (in-place)
    bn_apply_kernel<<<ROWS_A, 128>>>(Yq, DQK_, sum_q, sq_q, cnt + 0, gq, betaq, a_lens, LA_, 1, 0, nullptr);
    bn_apply_kernel<<<ROWS_B, 128>>>(Yk, DQK_, sum_k, sq_k, cnt + 1, gk, betak, b_lens, LB_, 1, 0, nullptr);
    bn_apply_kernel<<<ROWS_B, 128>>>(Yv, DV_,  sum_v, sq_v, cnt + 1, gv, betav, b_lens, LB_, 1, 0, nullptr);

    // 4) attention
    attention_kernel<<<dim3(S_, LA_ / 16), 256, ATT_SMEM_BYTES>>>(Yq, Yk, Yv, b_lens, Ywv);

    // 5) final projection + masked BN + ReLU + output mask
    gemm_nt<<<dim3(DQ_ / GBN, ROWS_A / GBM), 256>>>(Ywv, Wf, bf, Yf, ROWS_A, DQ_, DV_);
    stats_kernel<<<128, 256>>>(Yf, a_lens, LA_, ROWS_A, DQ_, 256, sum_f, sq_f);
    bn_apply_kernel<<<ROWS_A, 128>>>(Yf, DQ_, sum_f, sq_f, cnt + 0, gf, betaf, a_lens, LA_, 0, 1, out);
}

// round 2
// speedup vs baseline: 1.2762x; 1.2762x over previous
#include <cuda_runtime.h>
#include <cuda_bf16.h>
#include <math.h>
#include <stdint.h>

// ---------------------------------------------------------------------------
// Problem constants
// ---------------------------------------------------------------------------
#define S_   256
#define LA_  128
#define LB_  512
#define DQ_  256
#define DKV_ 265
#define DQK_ 512
#define DV_  512
#define KPAD 272            // DKV_ padded to multiple of 16

#define ROWS_A (S_ * LA_)   // 32768
#define ROWS_B (S_ * LB_)   // 131072

// Scratch (device globals; no allocation allowed)
__device__ float g_Yq [(size_t)ROWS_A * DQK_];
__device__ float g_Yk [(size_t)ROWS_B * DQK_];
__device__ float g_Yv [(size_t)ROWS_B * DV_];
__device__ float g_Ywv[(size_t)ROWS_A * DV_];
__device__ float g_Yf [(size_t)ROWS_A * DQ_];
__device__ float g_Bp [(size_t)ROWS_B * KPAD];   // padded B
__device__ float g_Wkp[512 * KPAD];
__device__ float g_Wvp[512 * KPAD];
__device__ float g_stats[8 * 512];
__device__ float g_cnt[2];

// ---------------------------------------------------------------------------
// Small init kernels
// ---------------------------------------------------------------------------
__global__ void zero_stats_kernel() {
    int i = blockIdx.x * blockDim.x + threadIdx.x;
    if (i < 8 * 512) g_stats[i] = 0.0f;
}

__global__ void cnt_kernel(const int* __restrict__ a_lens,
                           const int* __restrict__ b_lens) {
    __shared__ int sh[256];
    int t = threadIdx.x;
    sh[t] = a_lens[t];
    __syncthreads();
    for (int o = 128; o; o >>= 1) { if (t < o) sh[t] += sh[t + o]; __syncthreads(); }
    if (t == 0) g_cnt[0] = (float)sh[0];
    __syncthreads();
    sh[t] = b_lens[t];
    __syncthreads();
    for (int o = 128; o; o >>= 1) { if (t < o) sh[t] += sh[t + o]; __syncthreads(); }
    if (t == 0) g_cnt[1] = (float)sh[0];
}

// Pad rows of length Ksrc to KPAD (zero fill). One block per row.
__global__ void pad_kernel(const float* __restrict__ src, float* __restrict__ dst,
                           int Ksrc) {
    size_t r = blockIdx.x;
    for (int k = threadIdx.x; k < KPAD; k += blockDim.x)
        dst[r * KPAD + k] = (k < Ksrc) ? src[r * Ksrc + k] : 0.0f;
}

// ---------------------------------------------------------------------------
// Tensor-core GEMM (tf32 split, near-fp32 accuracy):
//   C[M,N] = X[M,K] @ W[N,K]^T + bias
// Requirements: M%128==0, N%64==0, K%16==0, X/W rows 16B-aligned.
// Block: 256 threads = 8 warps (4 m-rows x 2 n-cols), warp tile 32x32,
// mma.m16n8k8 tf32 with hi+lo split (3 mma per tile-step).
// ---------------------------------------------------------------------------
#define TBM 128
#define TBN 64
#define TBK 16
#define TST 20   // smem row stride in words (conflict-free, 16B-aligned rows)

__device__ __forceinline__ uint32_t f2tf(float x) {
    uint32_t u; asm("cvt.rna.tf32.f32 %0, %1;" : "=r"(u) : "f"(x)); return u;
}

#define MMA_TF32(c, a, b)                                                 \
  asm volatile("mma.sync.aligned.m16n8k8.row.col.f32.tf32.tf32.f32 "      \
    "{%0,%1,%2,%3}, {%4,%5,%6,%7}, {%8,%9}, {%0,%1,%2,%3};"               \
    : "+f"(c[0]), "+f"(c[1]), "+f"(c[2]), "+f"(c[3])                      \
    : "r"(a[0]), "r"(a[1]), "r"(a[2]), "r"(a[3]), "r"(b[0]), "r"(b[1]))

__global__ __launch_bounds__(256)
void gemm_tc(const float* __restrict__ X, const float* __restrict__ W,
             const float* __restrict__ bias, float* __restrict__ C,
             int M, int N, int K) {
    __shared__ uint32_t Xh[TBM][TST], Xl[TBM][TST];
    __shared__ uint32_t Wh[TBN][TST], Wl[TBN][TST];

    int tid  = threadIdx.x;
    int warp = tid >> 5, lane = tid & 31;
    int wm = warp >> 1;          // 0..3
    int wn = warp & 1;           // 0..1
    int g  = lane >> 2, tig = lane & 3;
    size_t row0 = (size_t)blockIdx.y * TBM;
    int    col0 = blockIdx.x * TBN;

    float c[2][4][4];
#pragma unroll
    for (int mt = 0; mt < 2; mt++)
#pragma unroll
        for (int nt = 0; nt < 4; nt++)
#pragma unroll
            for (int i = 0; i < 4; i++) c[mt][nt][i] = 0.0f;

    int xr = tid >> 1;           // 0..127
    int xk = (tid & 1) * 8;      // 0 or 8
    int wr = tid >> 2;           // 0..63
    int wk = (tid & 3) * 4;      // 0,4,8,12

    const float* Xp = X + (row0 + xr) * (size_t)K + xk;
    const float* Wp = W + (size_t)(col0 + wr) * K + wk;

    for (int k0 = 0; k0 < K; k0 += TBK) {
        // --- stage tiles: split each fp32 into tf32 hi + lo ---
        float4 v0 = *reinterpret_cast<const float4*>(Xp + k0);
        float4 v1 = *reinterpret_cast<const float4*>(Xp + k0 + 4);
        float4 w0 = *reinterpret_cast<const float4*>(Wp + k0);
        float xv[8] = {v0.x, v0.y, v0.z, v0.w, v1.x, v1.y, v1.z, v1.w};
#pragma unroll
        for (int j = 0; j < 8; j++) {
            uint32_t h = f2tf(xv[j]);
            Xh[xr][xk + j] = h;
            Xl[xr][xk + j] = f2tf(xv[j] - __uint_as_float(h));
        }
        float wv4[4] = {w0.x, w0.y, w0.z, w0.w};
#pragma unroll
        for (int j = 0; j < 4; j++) {
            uint32_t h = f2tf(wv4[j]);
            Wh[wr][wk + j] = h;
            Wl[wr][wk + j] = f2tf(wv4[j] - __uint_as_float(h));
        }
        __syncthreads();

#pragma unroll
        for (int ks = 0; ks < 2; ks++) {
            int kb = ks * 8;
            uint32_t ah[2][4], al[2][4], bh[4][2], bl[4][2];
#pragma unroll
            for (int mt = 0; mt < 2; mt++) {
                int r = wm * 32 + mt * 16 + g;
                ah[mt][0] = Xh[r][kb + tig];       al[mt][0] = Xl[r][kb + tig];
                ah[mt][1] = Xh[r + 8][kb + tig];   al[mt][1] = Xl[r + 8][kb + tig];
                ah[mt][2] = Xh[r][kb + tig + 4];   al[mt][2] = Xl[r][kb + tig + 4];
                ah[mt][3] = Xh[r + 8][kb + tig + 4]; al[mt][3] = Xl[r + 8][kb + tig + 4];
            }
#pragma unroll
            for (int nt = 0; nt < 4; nt++) {
                int n = wn * 32 + nt * 8 + g;
                bh[nt][0] = Wh[n][kb + tig];       bl[nt][0] = Wl[n][kb + tig];
                bh[nt][1] = Wh[n][kb + tig + 4];   bl[nt][1] = Wl[n][kb + tig + 4];
            }
#pragma unroll
            for (int mt = 0; mt < 2; mt++)
#pragma unroll
                for (int nt = 0; nt < 4; nt++) {
                    MMA_TF32(c[mt][nt], ah[mt], bh[nt]);   // hi*hi
                    MMA_TF32(c[mt][nt], ah[mt], bl[nt]);   // hi*lo
                    MMA_TF32(c[mt][nt], al[mt], bh[nt]);   // lo*hi
                }
        }
        __syncthreads();
    }

    // --- epilogue: += bias, write C ---
#pragma unroll
    for (int mt = 0; mt < 2; mt++) {
        size_t r0 = row0 + wm * 32 + mt * 16 + g;
#pragma unroll
        for (int nt = 0; nt < 4; nt++) {
            int cc = col0 + wn * 32 + nt * 8 + tig * 2;
            float b0 = bias[cc], b1 = bias[cc + 1];
            C[r0 * N + cc]           = c[mt][nt][0] + b0;
            C[r0 * N + cc + 1]       = c[mt][nt][1] + b1;
            C[(r0 + 8) * N + cc]     = c[mt][nt][2] + b0;
            C[(r0 + 8) * N + cc + 1] = c[mt][nt][3] + b1;
        }
    }
}

// ---------------------------------------------------------------------------
// Masked per-channel sum / sumsq over rows.
// ---------------------------------------------------------------------------
__global__ __launch_bounds__(256)
void stats_kernel(const float* __restrict__ Y, const int* __restrict__ lens,
                  int L, int nRows, int D, int rowsPerBlock,
                  float* __restrict__ sumOut, float* __restrict__ sqOut) {
    int r0 = blockIdx.x * rowsPerBlock;
    int r1 = min(r0 + rowsPerBlock, nRows);
    int c0 = threadIdx.x;
    int c1 = threadIdx.x + 256;

    float s0 = 0.f, q0 = 0.f, s1 = 0.f, q1 = 0.f;
    for (int r = r0; r < r1; r++) {
        int sidx = r / L;
        int l    = r - sidx * L;
        if (l >= lens[sidx]) continue;
        const float* row = Y + (size_t)r * D;
        float v = row[c0]; s0 += v; q0 += v * v;
        if (c1 < D) { float w = row[c1]; s1 += w; q1 += w * w; }
    }
    atomicAdd(&sumOut[c0], s0);
    atomicAdd(&sqOut[c0],  q0);
    if (c1 < D) {
        atomicAdd(&sumOut[c1], s1);
        atomicAdd(&sqOut[c1],  q1);
    }
}

// ---------------------------------------------------------------------------
// BN apply + ReLU + optional L2 row-normalize + optional row mask.
// ---------------------------------------------------------------------------
__global__ __launch_bounds__(128)
void bn_apply_kernel(float* __restrict__ Y, int D,
                     const float* __restrict__ ssum, const float* __restrict__ ssq,
                     const float* __restrict__ cntp,
                     const float* __restrict__ gamma, const float* __restrict__ beta,
                     const int* __restrict__ lens, int L,
                     int normalize, int maskOut, float* __restrict__ out) {
    int r = blockIdx.x;
    int sidx = r / L;
    int l    = r - sidx * L;
    bool valid = (l < lens[sidx]);

    float inv = 1.0f / (*cntp);
    int t = threadIdx.x;
    int per = D >> 7;

    float vals[4];
    float ss = 0.0f;
#pragma unroll 4
    for (int i = 0; i < per; i++) {
        int c = t + (i << 7);
        float mean = ssum[c] * inv;
        float var  = ssq[c] * inv - mean * mean;
        var = fmaxf(var, 0.0f);
        float z = (Y[(size_t)r * D + c] - mean) * rsqrtf(var + 1e-5f) * gamma[c] + beta[c];
        z = fmaxf(z, 0.0f);
        vals[i] = z;
        ss += z * z;
    }

    __shared__ float red[4];
#pragma unroll
    for (int o = 16; o; o >>= 1) ss += __shfl_xor_sync(0xffffffffu, ss, o);
    if ((t & 31) == 0) red[t >> 5] = ss;
    __syncthreads();
    float tot = red[0] + red[1] + red[2] + red[3];

    float scale = 1.0f;
    if (normalize) scale = 1.0f / fmaxf(sqrtf(tot), 1e-12f);
    if (maskOut && !valid) scale = 0.0f;

    float* dst = out ? out : Y;
#pragma unroll 4
    for (int i = 0; i < per; i++) {
        int c = t + (i << 7);
        dst[(size_t)r * D + c] = vals[i] * scale;
    }
}

// ---------------------------------------------------------------------------
// Attention (unchanged from R1): per block (s, 16-row q tile), fp32 SIMT.
// ---------------------------------------------------------------------------
#define KS_STRIDE 513
#define ATT_SMEM_FLOATS (16 * 512 + 32 * KS_STRIDE + 16 * 33)
#define ATT_SMEM_BYTES  (ATT_SMEM_FLOATS * 4)

__global__ __launch_bounds__(256)
void attention_kernel(const float* __restrict__ q, const float* __restrict__ k,
                      const float* __restrict__ v, const int* __restrict__ b_lens,
                      float* __restrict__ wv) {
    extern __shared__ float smem[];
    float* sS   = smem;
    float* sBuf = smem + 16 * 512;
    float* sQ   = sBuf + 32 * KS_STRIDE;

    int s   = blockIdx.x;
    int a0  = blockIdx.y * 16;
    int tid = threadIdx.x;
    int ty  = tid >> 6;
    int tx  = tid & 63;
    int nb  = b_lens[s];

    const float* qs = q + ((size_t)s * LA_ + a0) * DQK_;
    const float* ks = k + (size_t)s * LB_ * DQK_;
    const float* vs = v + (size_t)s * LB_ * DV_;

    float acc[4][8];
#pragma unroll
    for (int i = 0; i < 4; i++)
#pragma unroll
        for (int j = 0; j < 8; j++) acc[i][j] = 0.0f;

    for (int d0 = 0; d0 < DQK_; d0 += 32) {
        {
            int idx = tid * 2;
            int r = idx >> 5, kk = idx & 31;
            sQ[r * 33 + kk]     = qs[r * DQK_ + d0 + kk];
            sQ[r * 33 + kk + 1] = qs[r * DQK_ + d0 + kk + 1];
        }
#pragma unroll
        for (int i = 0; i < 16; i++) {
            int idx = tid + 256 * i;
            int b = idx >> 3, f4 = idx & 7;
            float4 kv = *reinterpret_cast<const float4*>(ks + (size_t)b * DQK_ + d0 + f4 * 4);
            sBuf[(f4 * 4 + 0) * KS_STRIDE + b] = kv.x;
            sBuf[(f4 * 4 + 1) * KS_STRIDE + b] = kv.y;
            sBuf[(f4 * 4 + 2) * KS_STRIDE + b] = kv.z;
            sBuf[(f4 * 4 + 3) * KS_STRIDE + b] = kv.w;
        }
        __syncthreads();

#pragma unroll
        for (int kk = 0; kk < 32; kk++) {
            float qr[4], kr[8];
#pragma unroll
            for (int i = 0; i < 4; i++) qr[i] = sQ[(ty * 4 + i) * 33 + kk];
#pragma unroll
            for (int j = 0; j < 8; j++) kr[j] = sBuf[kk * KS_STRIDE + tx + 64 * j];
#pragma unroll
            for (int i = 0; i < 4; i++)
#pragma unroll
                for (int j = 0; j < 8; j++)
                    acc[i][j] = fmaf(qr[i], kr[j], acc[i][j]);
        }
        __syncthreads();
    }

    const float scaler = 6.25f;
#pragma unroll
    for (int i = 0; i < 4; i++)
#pragma unroll
        for (int j = 0; j < 8; j++) {
            int b = tx + 64 * j;
            float val = acc[i][j] * scaler;
            if (b >= nb) val = -1e30f;
            sS[(ty * 4 + i) * 512 + b] = val;
        }
    __syncthreads();

    {
        int w = tid >> 5, lane = tid & 31;
#pragma unroll
        for (int rr = 0; rr < 2; rr++) {
            int row = w * 2 + rr;
            float m = -1e30f;
            for (int c = lane; c < 512; c += 32) m = fmaxf(m, sS[row * 512 + c]);
#pragma unroll
            for (int o = 16; o; o >>= 1) m = fmaxf(m, __shfl_xor_sync(0xffffffffu, m, o));
            float sum = 0.0f;
            for (int c = lane; c < 512; c += 32) {
                float e = expf(sS[row * 512 + c] - m);
                sS[row * 512 + c] = e;
                sum += e;
            }
#pragma unroll
            for (int o = 16; o; o >>= 1) sum += __shfl_xor_sync(0xffffffffu, sum, o);
            float invs = 1.0f / sum;
            for (int c = lane; c < 512; c += 32) sS[row * 512 + c] *= invs;
        }
    }
    __syncthreads();

#pragma unroll
    for (int i = 0; i < 4; i++)
#pragma unroll
        for (int j = 0; j < 8; j++) acc[i][j] = 0.0f;

    for (int b0 = 0; b0 < LB_; b0 += 32) {
#pragma unroll
        for (int i = 0; i < 16; i++) {
            int idx = tid + 256 * i;
            int kk = idx >> 7, f4 = idx & 127;
            float4 vv = *reinterpret_cast<const float4*>(vs + (size_t)(b0 + kk) * DV_ + f4 * 4);
            *reinterpret_cast<float4*>(&sBuf[kk * 512 + f4 * 4]) = vv;
        }
        __syncthreads();

#pragma unroll
        for (int kk = 0; kk < 32; kk++) {
            float wr[4], vr[8];
#pragma unroll
            for (int i = 0; i < 4; i++) wr[i] = sS[(ty * 4 + i) * 512 + b0 + kk];
#pragma unroll
            for (int j = 0; j < 8; j++) vr[j] = sBuf[kk * 512 + tx + 64 * j];
#pragma unroll
            for (int i = 0; i < 4; i++)
#pragma unroll
                for (int j = 0; j < 8; j++)
                    acc[i][j] = fmaf(wr[i], vr[j], acc[i][j]);
        }
        __syncthreads();
    }

    float* wvp = wv + ((size_t)s * LA_ + a0) * DV_;
#pragma unroll
    for (int i = 0; i < 4; i++)
#pragma unroll
        for (int j = 0; j < 8; j++)
            wvp[(ty * 4 + i) * DV_ + tx + 64 * j] = acc[i][j];
}

// ---------------------------------------------------------------------------
// Launch
// ---------------------------------------------------------------------------
extern "C" void kernel_launch(void* const* d_in, const int* in_sizes, int n_in,
                              void* d_out, int out_size) {
    const float* A      = (const float*)d_in[0];
    const float* B      = (const float*)d_in[1];
    const int*   a_lens = (const int*)  d_in[2];
    const int*   b_lens = (const int*)  d_in[3];
    const float* Wq     = (const float*)d_in[4];
    const float* bq     = (const float*)d_in[5];
    const float* gq     = (const float*)d_in[6];
    const float* betaq  = (const float*)d_in[7];
    const float* Wk     = (const float*)d_in[8];
    const float* bk     = (const float*)d_in[9];
    const float* gk     = (const float*)d_in[10];
    const float* betak  = (const float*)d_in[11];
    const float* Wv     = (const float*)d_in[12];
    const float* bv     = (const float*)d_in[13];
    const float* gv     = (const float*)d_in[14];
    const float* betav  = (const float*)d_in[15];
    const float* Wf     = (const float*)d_in[16];
    const float* bf     = (const float*)d_in[17];
    const float* gf     = (const float*)d_in[18];
    const float* betaf  = (const float*)d_in[19];
    float* out = (float*)d_out;

    float *Yq, *Yk, *Yv, *Ywv, *Yf, *Bp, *Wkp, *Wvp, *stats, *cnt;
    cudaGetSymbolAddress((void**)&Yq,   g_Yq);
    cudaGetSymbolAddress((void**)&Yk,   g_Yk);
    cudaGetSymbolAddress((void**)&Yv,   g_Yv);
    cudaGetSymbolAddress((void**)&Ywv,  g_Ywv);
    cudaGetSymbolAddress((void**)&Yf,   g_Yf);
    cudaGetSymbolAddress((void**)&Bp,   g_Bp);
    cudaGetSymbolAddress((void**)&Wkp,  g_Wkp);
    cudaGetSymbolAddress((void**)&Wvp,  g_Wvp);
    cudaGetSymbolAddress((void**)&stats, g_stats);
    cudaGetSymbolAddress((void**)&cnt,  g_cnt);

    cudaFuncSetAttribute(attention_kernel,
                         cudaFuncAttributeMaxDynamicSharedMemorySize, ATT_SMEM_BYTES);

    float* sum_q = stats + 0 * 512;
    float* sq_q  = stats + 1 * 512;
    float* sum_k = stats + 2 * 512;
    float* sq_k  = stats + 3 * 512;
    float* sum_v = stats + 4 * 512;
    float* sq_v  = stats + 5 * 512;
    float* sum_f = stats + 6 * 512;
    float* sq_f  = stats + 7 * 512;

    // 0) reset accumulators + pad odd-K operands
    zero_stats_kernel<<<16, 256>>>();
    cnt_kernel<<<1, 256>>>(a_lens, b_lens);
    pad_kernel<<<ROWS_B, 256>>>(B,  Bp,  DKV_);
    pad_kernel<<<512, 256>>>(Wk, Wkp, DKV_);
    pad_kernel<<<512, 256>>>(Wv, Wvp, DKV_);

    // 1) projection GEMMs (tf32-split tensor core)
    gemm_tc<<<dim3(DQK_ / TBN, ROWS_A / TBM), 256>>>(A,  Wq,  bq, Yq, ROWS_A, DQK_, DQ_);
    gemm_tc<<<dim3(DQK_ / TBN, ROWS_B / TBM), 256>>>(Bp, Wkp, bk, Yk, ROWS_B, DQK_, KPAD);
    gemm_tc<<<dim3(DV_  / TBN, ROWS_B / TBM), 256>>>(Bp, Wvp, bv, Yv, ROWS_B, DV_,  KPAD);

    // 2) masked BN stats
    stats_kernel<<<128, 256>>>(Yq, a_lens, LA_, ROWS_A, DQK_, 256, sum_q, sq_q);
    stats_kernel<<<512, 256>>>(Yk, b_lens, LB_, ROWS_B, DQK_, 256, sum_k, sq_k);
    stats_kernel<<<512, 256>>>(Yv, b_lens, LB_, ROWS_B, DV_,  256, sum_v, sq_v);

    // 3) BN + ReLU + L2-normalize (in-place)
    bn_apply_kernel<<<ROWS_A, 128>>>(Yq, DQK_, sum_q, sq_q, cnt + 0, gq, betaq, a_lens, LA_, 1, 0, nullptr);
    bn_apply_kernel<<<ROWS_B, 128>>>(Yk, DQK_, sum_k, sq_k, cnt + 1, gk, betak, b_lens, LB_, 1, 0, nullptr);
    bn_apply_kernel<<<ROWS_B, 128>>>(Yv, DV_,  sum_v, sq_v, cnt + 1, gv, betav, b_lens, LB_, 1, 0, nullptr);

    // 4) attention
    attention_kernel<<<dim3(S_, LA_ / 16), 256, ATT_SMEM_BYTES>>>(Yq, Yk, Yv, b_lens, Ywv);

    // 5) final projection + masked BN + ReLU + output mask
    gemm_tc<<<dim3(DQ_ / TBN, ROWS_A / TBM), 256>>>(Ywv, Wf, bf, Yf, ROWS_A, DQ_, DV_);
    stats_kernel<<<128, 256>>>(Yf, a_lens, LA_, ROWS_A, DQ_, 256, sum_f, sq_f);
    bn_apply_kernel<<<ROWS_A, 128>>>(Yf, DQ_, sum_f, sq_f, cnt + 0, gf, betaf, a_lens, LA_, 0, 1, out);
}

// round 3
// speedup vs baseline: 1.6636x; 1.3036x over previous
#include <cuda_runtime.h>
#include <cuda_bf16.h>
#include <math.h>
#include <stdint.h>

// ---------------------------------------------------------------------------
// Problem constants
// ---------------------------------------------------------------------------
#define S_   256
#define LA_  128
#define LB_  512
#define DQ_  256
#define DKV_ 265
#define DQK_ 512
#define DV_  512
#define KPAD 272            // DKV_ padded to multiple of 16

#define ROWS_A (S_ * LA_)   // 32768
#define ROWS_B (S_ * LB_)   // 131072

// Scratch (device globals; no allocation allowed)
__device__ float g_Yq [(size_t)ROWS_A * DQK_];
__device__ float g_Yk [(size_t)ROWS_B * DQK_];
__device__ float g_Yv [(size_t)ROWS_B * DV_];
__device__ float g_Ywv[(size_t)ROWS_A * DV_];
__device__ float g_Yf [(size_t)ROWS_A * DQ_];
__device__ float g_Bp [(size_t)ROWS_B * KPAD];   // padded B
__device__ float g_Wkp[512 * KPAD];
__device__ float g_Wvp[512 * KPAD];
__device__ float g_stats[8 * 512];
__device__ float g_cnt[2];

// ---------------------------------------------------------------------------
// Helpers: tf32 split + mma + cp.async
// ---------------------------------------------------------------------------
__device__ __forceinline__ uint32_t f2tf(float x) {
    uint32_t u; asm("cvt.rna.tf32.f32 %0, %1;" : "=r"(u) : "f"(x)); return u;
}
__device__ __forceinline__ void splitf(float x, uint32_t& h, uint32_t& l) {
    h = f2tf(x);
    l = f2tf(x - __uint_as_float(h));
}

#define MMA_TF32(c, a, b)                                                 \
  asm volatile("mma.sync.aligned.m16n8k8.row.col.f32.tf32.tf32.f32 "      \
    "{%0,%1,%2,%3}, {%4,%5,%6,%7}, {%8,%9}, {%0,%1,%2,%3};"               \
    : "+f"(c[0]), "+f"(c[1]), "+f"(c[2]), "+f"(c[3])                      \
    : "r"(a[0]), "r"(a[1]), "r"(a[2]), "r"(a[3]), "r"(b[0]), "r"(b[1]))

#define CP_ASYNC16(smem_u32, gptr) \
  asm volatile("cp.async.cg.shared.global [%0], [%1], 16;" :: "r"(smem_u32), "l"(gptr))
#define CP_COMMIT() asm volatile("cp.async.commit_group;")
#define CP_WAIT1()  asm volatile("cp.async.wait_group 1;")
#define CP_WAIT0()  asm volatile("cp.async.wait_group 0;")

// ---------------------------------------------------------------------------
// Small init kernels
// ---------------------------------------------------------------------------
__global__ void zero_stats_kernel() {
    int i = blockIdx.x * blockDim.x + threadIdx.x;
    if (i < 8 * 512) g_stats[i] = 0.0f;
}

__global__ void cnt_kernel(const int* __restrict__ a_lens,
                           const int* __restrict__ b_lens) {
    __shared__ int sh[256];
    int t = threadIdx.x;
    sh[t] = a_lens[t];
    __syncthreads();
    for (int o = 128; o; o >>= 1) { if (t < o) sh[t] += sh[t + o]; __syncthreads(); }
    if (t == 0) g_cnt[0] = (float)sh[0];
    __syncthreads();
    sh[t] = b_lens[t];
    __syncthreads();
    for (int o = 128; o; o >>= 1) { if (t < o) sh[t] += sh[t + o]; __syncthreads(); }
    if (t == 0) g_cnt[1] = (float)sh[0];
}

// Pad rows of length Ksrc to KPAD (zero fill). One block per row.
__global__ void pad_kernel(const float* __restrict__ src, float* __restrict__ dst,
                           int Ksrc) {
    size_t r = blockIdx.x;
    for (int k = threadIdx.x; k < KPAD; k += blockDim.x)
        dst[r * KPAD + k] = (k < Ksrc) ? src[r * Ksrc + k] : 0.0f;
}

// ---------------------------------------------------------------------------
// Tensor-core GEMM v2 (tf32 split, raw-f32 smem, cp.async double buffer):
//   C[M,N] = X[M,K] @ W[N,K]^T + bias
// Requirements: M%128==0, N%64==0, K%16==0, rows 16B-aligned.
// 256 threads = 8 warps (4m x 2n), warp tile 32x32.
// ---------------------------------------------------------------------------
#define TBM 128
#define TBN 64
#define TBK 16
#define TST 20   // smem row stride (words); 80B rows -> 16B aligned, conflict-free frags

__global__ __launch_bounds__(256)
void gemm_tc(const float* __restrict__ X, const float* __restrict__ W,
             const float* __restrict__ bias, float* __restrict__ C,
             int M, int N, int K) {
    __shared__ float Xs[2][TBM][TST];
    __shared__ float Ws[2][TBN][TST];

    int tid  = threadIdx.x;
    int warp = tid >> 5, lane = tid & 31;
    int wm = warp >> 1;          // 0..3
    int wn = warp & 1;           // 0..1
    int g  = lane >> 2, tig = lane & 3;
    size_t row0 = (size_t)blockIdx.y * TBM;
    int    col0 = blockIdx.x * TBN;

    float c[2][4][4];
#pragma unroll
    for (int mt = 0; mt < 2; mt++)
#pragma unroll
        for (int nt = 0; nt < 4; nt++)
#pragma unroll
            for (int i = 0; i < 4; i++) c[mt][nt][i] = 0.0f;

    int xr = tid >> 1;           // 0..127
    int xk = (tid & 1) * 8;      // 0 or 8
    int wr = tid >> 2;           // 0..63
    int wk = (tid & 3) * 4;      // 0,4,8,12

    const float* Xp = X + (row0 + xr) * (size_t)K + xk;
    const float* Wp = W + (size_t)(col0 + wr) * K + wk;

    uint32_t sx0 = (uint32_t)__cvta_generic_to_shared(&Xs[0][xr][xk]);
    uint32_t sx1 = (uint32_t)__cvta_generic_to_shared(&Xs[1][xr][xk]);
    uint32_t sw0 = (uint32_t)__cvta_generic_to_shared(&Ws[0][wr][wk]);
    uint32_t sw1 = (uint32_t)__cvta_generic_to_shared(&Ws[1][wr][wk]);

    int nk = K / TBK;

    // prologue: stage tile 0 into buf 0
    CP_ASYNC16(sx0,      Xp);
    CP_ASYNC16(sx0 + 16, Xp + 4);
    CP_ASYNC16(sw0,      Wp);
    CP_COMMIT();

    for (int i = 0; i < nk; i++) {
        int buf = i & 1;
        if (i + 1 < nk) {
            const float* xp = Xp + (size_t)(i + 1) * TBK;
            const float* wp = Wp + (size_t)(i + 1) * TBK;
            uint32_t dx = buf ? sx0 : sx1;
            uint32_t dw = buf ? sw0 : sw1;
            CP_ASYNC16(dx,      xp);
            CP_ASYNC16(dx + 16, xp + 4);
            CP_ASYNC16(dw,      wp);
            CP_COMMIT();
            CP_WAIT1();
        } else {
            CP_WAIT0();
        }
        __syncthreads();

#pragma unroll
        for (int ks = 0; ks < 2; ks++) {
            int kb = ks * 8;
            uint32_t ah[2][4], al[2][4];
#pragma unroll
            for (int mt = 0; mt < 2; mt++) {
                int r = wm * 32 + mt * 16 + g;
                splitf(Xs[buf][r][kb + tig],          ah[mt][0], al[mt][0]);
                splitf(Xs[buf][r + 8][kb + tig],      ah[mt][1], al[mt][1]);
                splitf(Xs[buf][r][kb + tig + 4],      ah[mt][2], al[mt][2]);
                splitf(Xs[buf][r + 8][kb + tig + 4],  ah[mt][3], al[mt][3]);
            }
#pragma unroll
            for (int nt = 0; nt < 4; nt++) {
                int n = wn * 32 + nt * 8 + g;
                uint32_t bh[2], bl[2];
                splitf(Ws[buf][n][kb + tig],     bh[0], bl[0]);
                splitf(Ws[buf][n][kb + tig + 4], bh[1], bl[1]);
#pragma unroll
                for (int mt = 0; mt < 2; mt++) {
                    MMA_TF32(c[mt][nt], ah[mt], bh);   // hi*hi
                    MMA_TF32(c[mt][nt], ah[mt], bl);   // hi*lo
                    MMA_TF32(c[mt][nt], al[mt], bh);   // lo*hi
                }
            }
        }
        __syncthreads();
    }

    // epilogue
#pragma unroll
    for (int mt = 0; mt < 2; mt++) {
        size_t r0 = row0 + wm * 32 + mt * 16 + g;
#pragma unroll
        for (int nt = 0; nt < 4; nt++) {
            int cc = col0 + wn * 32 + nt * 8 + tig * 2;
            float b0 = bias[cc], b1 = bias[cc + 1];
            C[r0 * N + cc]           = c[mt][nt][0] + b0;
            C[r0 * N + cc + 1]       = c[mt][nt][1] + b1;
            C[(r0 + 8) * N + cc]     = c[mt][nt][2] + b0;
            C[(r0 + 8) * N + cc + 1] = c[mt][nt][3] + b1;
        }
    }
}

// ---------------------------------------------------------------------------
// Tensor-core attention: one block per (s, 64-row q tile). 512 threads,
// 16 warps = 2m x 8n, warp tile 32x64. tf32 split everywhere.
//  Phase A: S[64][512] = Q K^T (K rows are already the col-major B operand)
//  softmax (warp per 4 rows), mask b >= b_lens[s]
//  Phase B: WV[64][512] = P V   (V staged transposed)
// ---------------------------------------------------------------------------
#define AST 516   // scores stride: 516 % 32 = 4 -> conflict-free A-frag loads
#define KST 20    // K / V^T chunk stride
#define ATT_SMEM_FLOATS (64 * AST + 512 * KST + 64 * KST)
#define ATT_SMEM_BYTES  (ATT_SMEM_FLOATS * 4)   // 178176 B

__global__ __launch_bounds__(512)
void attention_tc(const float* __restrict__ q, const float* __restrict__ k,
                  const float* __restrict__ v, const int* __restrict__ b_lens,
                  float* __restrict__ wv) {
    extern __shared__ float sm[];
    float* sS = sm;                    // [64][AST]
    float* sK = sm + 64 * AST;         // [512][KST]
    float* sQ = sK + 512 * KST;        // [64][KST]

    int s   = blockIdx.x;
    int a0  = blockIdx.y * 64;
    int tid = threadIdx.x;
    int warp = tid >> 5, lane = tid & 31;
    int wm = warp >> 3;                // 0..1
    int wn = warp & 7;                 // 0..7
    int g  = lane >> 2, tig = lane & 3;
    int nb = b_lens[s];

    const float* qs = q + ((size_t)s * LA_ + a0) * DQK_;
    const float* ks = k + (size_t)s * LB_ * DQK_;
    const float* vs = v + (size_t)s * LB_ * DV_;

    float c[2][8][4];
#pragma unroll
    for (int mt = 0; mt < 2; mt++)
#pragma unroll
        for (int nt = 0; nt < 8; nt++)
#pragma unroll
            for (int i = 0; i < 4; i++) c[mt][nt][i] = 0.0f;

    // ---------------- Phase A: S = Q K^T ----------------
    for (int d0 = 0; d0 < DQK_; d0 += 16) {
        {   // Q tile 64x16, float2 per thread
            int idx = tid * 2;
            int r = idx >> 4, cc = idx & 15;
            *reinterpret_cast<float2*>(&sQ[r * KST + cc]) =
                *reinterpret_cast<const float2*>(&qs[(size_t)r * DQK_ + d0 + cc]);
        }
        // K tile 512x16, float4 per slot
#pragma unroll
        for (int i = 0; i < 4; i++) {
            int idx = tid + 512 * i;
            int b = idx >> 2, c4 = (idx & 3) * 4;
            *reinterpret_cast<float4*>(&sK[b * KST + c4]) =
                *reinterpret_cast<const float4*>(&ks[(size_t)b * DQK_ + d0 + c4]);
        }
        __syncthreads();

#pragma unroll
        for (int ks8 = 0; ks8 < 2; ks8++) {
            int kb = ks8 * 8;
            uint32_t ah[2][4], al[2][4];
#pragma unroll
            for (int mt = 0; mt < 2; mt++) {
                int r = wm * 32 + mt * 16 + g;
                splitf(sQ[r * KST + kb + tig],           ah[mt][0], al[mt][0]);
                splitf(sQ[(r + 8) * KST + kb + tig],     ah[mt][1], al[mt][1]);
                splitf(sQ[r * KST + kb + tig + 4],       ah[mt][2], al[mt][2]);
                splitf(sQ[(r + 8) * KST + kb + tig + 4], ah[mt][3], al[mt][3]);
            }
#pragma unroll
            for (int nt = 0; nt < 8; nt++) {
                int n = wn * 64 + nt * 8 + g;
                uint32_t bh[2], bl[2];
                splitf(sK[n * KST + kb + tig],     bh[0], bl[0]);
                splitf(sK[n * KST + kb + tig + 4], bh[1], bl[1]);
#pragma unroll
                for (int mt = 0; mt < 2; mt++) {
                    MMA_TF32(c[mt][nt], ah[mt], bh);
                    MMA_TF32(c[mt][nt], ah[mt], bl);
                    MMA_TF32(c[mt][nt], al[mt], bh);
                }
            }
        }
        __syncthreads();
    }

    // scale + mask -> sS
    const float scaler = 6.25f;   // 1 / (0.01 * sqrt(256))
#pragma unroll
    for (int mt = 0; mt < 2; mt++) {
        int r = wm * 32 + mt * 16 + g;
#pragma unroll
        for (int nt = 0; nt < 8; nt++) {
            int col = wn * 64 + nt * 8 + tig * 2;
            float v0 = c[mt][nt][0] * scaler;
            float v1 = c[mt][nt][1] * scaler;
            float v2 = c[mt][nt][2] * scaler;
            float v3 = c[mt][nt][3] * scaler;
            sS[r * AST + col]           = (col     < nb) ? v0 : -1e30f;
            sS[r * AST + col + 1]       = (col + 1 < nb) ? v1 : -1e30f;
            sS[(r + 8) * AST + col]     = (col     < nb) ? v2 : -1e30f;
            sS[(r + 8) * AST + col + 1] = (col + 1 < nb) ? v3 : -1e30f;
        }
    }
    __syncthreads();

    // ---------------- softmax: warp per 4 rows ----------------
#pragma unroll
    for (int rr = 0; rr < 4; rr++) {
        int row = warp * 4 + rr;
        float m = -1e30f;
        for (int cc = lane; cc < 512; cc += 32) m = fmaxf(m, sS[row * AST + cc]);
#pragma unroll
        for (int o = 16; o; o >>= 1) m = fmaxf(m, __shfl_xor_sync(0xffffffffu, m, o));
        float sum = 0.0f;
        for (int cc = lane; cc < 512; cc += 32) {
            float e = expf(sS[row * AST + cc] - m);
            sS[row * AST + cc] = e;
            sum += e;
        }
#pragma unroll
        for (int o = 16; o; o >>= 1) sum += __shfl_xor_sync(0xffffffffu, sum, o);
        float invs = 1.0f / sum;
        for (int cc = lane; cc < 512; cc += 32) sS[row * AST + cc] *= invs;
    }
    __syncthreads();

    // ---------------- Phase B: WV = P V ----------------
#pragma unroll
    for (int mt = 0; mt < 2; mt++)
#pragma unroll
        for (int nt = 0; nt < 8; nt++)
#pragma unroll
            for (int i = 0; i < 4; i++) c[mt][nt][i] = 0.0f;

    for (int b0 = 0; b0 < LB_; b0 += 16) {
        // stage V^T chunk: [512 d][16 b]
#pragma unroll
        for (int i = 0; i < 4; i++) {
            int idx = tid + 512 * i;
            int kk = idx & 15, dg = idx >> 4;
            float4 vv = *reinterpret_cast<const float4*>(
                &vs[(size_t)(b0 + kk) * DV_ + dg * 4]);
            sK[(dg * 4 + 0) * KST + kk] = vv.x;
            sK[(dg * 4 + 1) * KST + kk] = vv.y;
            sK[(dg * 4 + 2) * KST + kk] = vv.z;
            sK[(dg * 4 + 3) * KST + kk] = vv.w;
        }
        __syncthreads();

#pragma unroll
        for (int ks8 = 0; ks8 < 2; ks8++) {
            int kb = ks8 * 8;
            uint32_t ah[2][4], al[2][4];
#pragma unroll
            for (int mt = 0; mt < 2; mt++) {
                int r = wm * 32 + mt * 16 + g;
                splitf(sS[r * AST + b0 + kb + tig],           ah[mt][0], al[mt][0]);
                splitf(sS[(r + 8) * AST + b0 + kb + tig],     ah[mt][1], al[mt][1]);
                splitf(sS[r * AST + b0 + kb + tig + 4],       ah[mt][2], al[mt][2]);
                splitf(sS[(r + 8) * AST + b0 + kb + tig + 4], ah[mt][3], al[mt][3]);
            }
#pragma unroll
            for (int nt = 0; nt < 8; nt++) {
                int n = wn * 64 + nt * 8 + g;
                uint32_t bh[2], bl[2];
                splitf(sK[n * KST + kb + tig],     bh[0], bl[0]);
                splitf(sK[n * KST + kb + tig + 4], bh[1], bl[1]);
#pragma unroll
                for (int mt = 0; mt < 2; mt++) {
                    MMA_TF32(c[mt][nt], ah[mt], bh);
                    MMA_TF32(c[mt][nt], ah[mt], bl);
                    MMA_TF32(c[mt][nt], al[mt], bh);
                }
            }
        }
        __syncthreads();
    }

    float* wvp = wv + ((size_t)s * LA_ + a0) * DV_;
#pragma unroll
    for (int mt = 0; mt < 2; mt++) {
        int r = wm * 32 + mt * 16 + g;
#pragma unroll
        for (int nt = 0; nt < 8; nt++) {
            int col = wn * 64 + nt * 8 + tig * 2;
            wvp[(size_t)r * DV_ + col]           = c[mt][nt][0];
            wvp[(size_t)r * DV_ + col + 1]       = c[mt][nt][1];
            wvp[(size_t)(r + 8) * DV_ + col]     = c[mt][nt][2];
            wvp[(size_t)(r + 8) * DV_ + col + 1] = c[mt][nt][3];
        }
    }
}

// ---------------------------------------------------------------------------
// Masked per-channel sum / sumsq over rows.
// ---------------------------------------------------------------------------
__global__ __launch_bounds__(256)
void stats_kernel(const float* __restrict__ Y, const int* __restrict__ lens,
                  int L, int nRows, int D, int rowsPerBlock,
                  float* __restrict__ sumOut, float* __restrict__ sqOut) {
    int r0 = blockIdx.x * rowsPerBlock;
    int r1 = min(r0 + rowsPerBlock, nRows);
    int c0 = threadIdx.x;
    int c1 = threadIdx.x + 256;

    float s0 = 0.f, q0 = 0.f, s1 = 0.f, q1 = 0.f;
    for (int r = r0; r < r1; r++) {
        int sidx = r / L;
        int l    = r - sidx * L;
        if (l >= lens[sidx]) continue;
        const float* row = Y + (size_t)r * D;
        float v = row[c0]; s0 += v; q0 += v * v;
        if (c1 < D) { float w = row[c1]; s1 += w; q1 += w * w; }
    }
    atomicAdd(&sumOut[c0], s0);
    atomicAdd(&sqOut[c0],  q0);
    if (c1 < D) {
        atomicAdd(&sumOut[c1], s1);
        atomicAdd(&sqOut[c1],  q1);
    }
}

// ---------------------------------------------------------------------------
// BN apply + ReLU + optional L2 row-normalize + optional row mask.
// ---------------------------------------------------------------------------
__global__ __launch_bounds__(128)
void bn_apply_kernel(float* __restrict__ Y, int D,
                     const float* __restrict__ ssum, const float* __restrict__ ssq,
                     const float* __restrict__ cntp,
                     const float* __restrict__ gamma, const float* __restrict__ beta,
                     const int* __restrict__ lens, int L,
                     int normalize, int maskOut, float* __restrict__ out) {
    int r = blockIdx.x;
    int sidx = r / L;
    int l    = r - sidx * L;
    bool valid = (l < lens[sidx]);

    float inv = 1.0f / (*cntp);
    int t = threadIdx.x;
    int per = D >> 7;

    float vals[4];
    float ss = 0.0f;
#pragma unroll 4
    for (int i = 0; i < per; i++) {
        int cc = t + (i << 7);
        float mean = ssum[cc] * inv;
        float var  = ssq[cc] * inv - mean * mean;
        var = fmaxf(var, 0.0f);
        float z = (Y[(size_t)r * D + cc] - mean) * rsqrtf(var + 1e-5f) * gamma[cc] + beta[cc];
        z = fmaxf(z, 0.0f);
        vals[i] = z;
        ss += z * z;
    }

    __shared__ float red[4];
#pragma unroll
    for (int o = 16; o; o >>= 1) ss += __shfl_xor_sync(0xffffffffu, ss, o);
    if ((t & 31) == 0) red[t >> 5] = ss;
    __syncthreads();
    float tot = red[0] + red[1] + red[2] + red[3];

    float scale = 1.0f;
    if (normalize) scale = 1.0f / fmaxf(sqrtf(tot), 1e-12f);
    if (maskOut && !valid) scale = 0.0f;

    float* dst = out ? out : Y;
#pragma unroll 4
    for (int i = 0; i < per; i++) {
        int cc = t + (i << 7);
        dst[(size_t)r * D + cc] = vals[i] * scale;
    }
}

// ---------------------------------------------------------------------------
// Launch
// ---------------------------------------------------------------------------
extern "C" void kernel_launch(void* const* d_in, const int* in_sizes, int n_in,
                              void* d_out, int out_size) {
    const float* A      = (const float*)d_in[0];
    const float* B      = (const float*)d_in[1];
    const int*   a_lens = (const int*)  d_in[2];
    const int*   b_lens = (const int*)  d_in[3];
    const float* Wq     = (const float*)d_in[4];
    const float* bq     = (const float*)d_in[5];
    const float* gq     = (const float*)d_in[6];
    const float* betaq  = (const float*)d_in[7];
    const float* Wk     = (const float*)d_in[8];
    const float* bk     = (const float*)d_in[9];
    const float* gk     = (const float*)d_in[10];
    const float* betak  = (const float*)d_in[11];
    const float* Wv     = (const float*)d_in[12];
    const float* bv     = (const float*)d_in[13];
    const float* gv     = (const float*)d_in[14];
    const float* betav  = (const float*)d_in[15];
    const float* Wf     = (const float*)d_in[16];
    const float* bf     = (const float*)d_in[17];
    const float* gf     = (const float*)d_in[18];
    const float* betaf  = (const float*)d_in[19];
    float* out = (float*)d_out;

    float *Yq, *Yk, *Yv, *Ywv, *Yf, *Bp, *Wkp, *Wvp, *stats, *cnt;
    cudaGetSymbolAddress((void**)&Yq,   g_Yq);
    cudaGetSymbolAddress((void**)&Yk,   g_Yk);
    cudaGetSymbolAddress((void**)&Yv,   g_Yv);
    cudaGetSymbolAddress((void**)&Ywv,  g_Ywv);
    cudaGetSymbolAddress((void**)&Yf,   g_Yf);
    cudaGetSymbolAddress((void**)&Bp,   g_Bp);
    cudaGetSymbolAddress((void**)&Wkp,  g_Wkp);
    cudaGetSymbolAddress((void**)&Wvp,  g_Wvp);
    cudaGetSymbolAddress((void**)&stats, g_stats);
    cudaGetSymbolAddress((void**)&cnt,  g_cnt);

    cudaFuncSetAttribute(attention_tc,
                         cudaFuncAttributeMaxDynamicSharedMemorySize, ATT_SMEM_BYTES);

    float* sum_q = stats + 0 * 512;
    float* sq_q  = stats + 1 * 512;
    float* sum_k = stats + 2 * 512;
    float* sq_k  = stats + 3 * 512;
    float* sum_v = stats + 4 * 512;
    float* sq_v  = stats + 5 * 512;
    float* sum_f = stats + 6 * 512;
    float* sq_f  = stats + 7 * 512;

    // 0) reset accumulators + pad odd-K operands
    zero_stats_kernel<<<16, 256>>>();
    cnt_kernel<<<1, 256>>>(a_lens, b_lens);
    pad_kernel<<<ROWS_B, 256>>>(B,  Bp,  DKV_);
    pad_kernel<<<512, 256>>>(Wk, Wkp, DKV_);
    pad_kernel<<<512, 256>>>(Wv, Wvp, DKV_);

    // 1) projection GEMMs
    gemm_tc<<<dim3(DQK_ / TBN, ROWS_A / TBM), 256>>>(A,  Wq,  bq, Yq, ROWS_A, DQK_, DQ_);
    gemm_tc<<<dim3(DQK_ / TBN, ROWS_B / TBM), 256>>>(Bp, Wkp, bk, Yk, ROWS_B, DQK_, KPAD);
    gemm_tc<<<dim3(DV_  / TBN, ROWS_B / TBM), 256>>>(Bp, Wvp, bv, Yv, ROWS_B, DV_,  KPAD);

    // 2) masked BN stats
    stats_kernel<<<128, 256>>>(Yq, a_lens, LA_, ROWS_A, DQK_, 256, sum_q, sq_q);
    stats_kernel<<<512, 256>>>(Yk, b_lens, LB_, ROWS_B, DQK_, 256, sum_k, sq_k);
    stats_kernel<<<512, 256>>>(Yv, b_lens, LB_, ROWS_B, DV_,  256, sum_v, sq_v);

    // 3) BN + ReLU + L2-normalize (in-place)
    bn_apply_kernel<<<ROWS_A, 128>>>(Yq, DQK_, sum_q, sq_q, cnt + 0, gq, betaq, a_lens, LA_, 1, 0, nullptr);
    bn_apply_kernel<<<ROWS_B, 128>>>(Yk, DQK_, sum_k, sq_k, cnt + 1, gk, betak, b_lens, LB_, 1, 0, nullptr);
    bn_apply_kernel<<<ROWS_B, 128>>>(Yv, DV_,  sum_v, sq_v, cnt + 1, gv, betav, b_lens, LB_, 1, 0, nullptr);

    // 4) attention (tensor core)
    attention_tc<<<dim3(S_, LA_ / 64), 512, ATT_SMEM_BYTES>>>(Yq, Yk, Yv, b_lens, Ywv);

    // 5) final projection + masked BN + ReLU + output mask
    gemm_tc<<<dim3(DQ_ / TBN, ROWS_A / TBM), 256>>>(Ywv, Wf, bf, Yf, ROWS_A, DQ_, DV_);
    stats_kernel<<<128, 256>>>(Yf, a_lens, LA_, ROWS_A, DQ_, 256, sum_f, sq_f);
    bn_apply_kernel<<<ROWS_A, 128>>>(Yf, DQ_, sum_f, sq_f, cnt + 0, gf, betaf, a_lens, LA_, 0, 1, out);
}

// round 4
// speedup vs baseline: 1.8630x; 1.1199x over previous
#include <cuda_runtime.h>
#include <cuda_bf16.h>
#include <math.h>
#include <stdint.h>

// ---------------------------------------------------------------------------
// Problem constants
// ---------------------------------------------------------------------------
#define S_   256
#define LA_  128
#define LB_  512
#define DQ_  256
#define DKV_ 265
#define DQK_ 512
#define DV_  512
#define KPAD 272            // DKV_ padded to multiple of 16

#define ROWS_A (S_ * LA_)   // 32768
#define ROWS_B (S_ * LB_)   // 131072

// Scratch (device globals; no allocation allowed)
__device__ float g_Yq [(size_t)ROWS_A * DQK_];
__device__ float g_Yk [(size_t)ROWS_B * DQK_];
__device__ float g_Yv [(size_t)ROWS_B * DV_];
__device__ float g_Ywv[(size_t)ROWS_A * DV_];
__device__ float g_Yf [(size_t)ROWS_A * DQ_];
__device__ float g_Bp [(size_t)ROWS_B * KPAD];   // padded B
__device__ float g_Wkp[512 * KPAD];
__device__ float g_Wvp[512 * KPAD];
__device__ float g_stats[8 * 512];
__device__ float g_cnt[2];

// ---------------------------------------------------------------------------
// Helpers: tf32 split + mma + cp.async
// ---------------------------------------------------------------------------
__device__ __forceinline__ uint32_t f2tf(float x) {
    uint32_t u; asm("cvt.rna.tf32.f32 %0, %1;" : "=r"(u) : "f"(x)); return u;
}
__device__ __forceinline__ void splitf(float x, uint32_t& h, uint32_t& l) {
    h = f2tf(x);
    l = f2tf(x - __uint_as_float(h));
}

#define MMA_TF32(c, a, b)                                                 \
  asm volatile("mma.sync.aligned.m16n8k8.row.col.f32.tf32.tf32.f32 "      \
    "{%0,%1,%2,%3}, {%4,%5,%6,%7}, {%8,%9}, {%0,%1,%2,%3};"               \
    : "+f"(c[0]), "+f"(c[1]), "+f"(c[2]), "+f"(c[3])                      \
    : "r"(a[0]), "r"(a[1]), "r"(a[2]), "r"(a[3]), "r"(b[0]), "r"(b[1]))

#define CP_ASYNC16(smem_u32, gptr) \
  asm volatile("cp.async.cg.shared.global [%0], [%1], 16;" :: "r"(smem_u32), "l"(gptr))
#define CP_COMMIT() asm volatile("cp.async.commit_group;")
#define CP_WAIT1()  asm volatile("cp.async.wait_group 1;")
#define CP_WAIT0()  asm volatile("cp.async.wait_group 0;")

// ---------------------------------------------------------------------------
// Small init kernels
// ---------------------------------------------------------------------------
__global__ void zero_stats_kernel() {
    int i = blockIdx.x * blockDim.x + threadIdx.x;
    if (i < 8 * 512) g_stats[i] = 0.0f;
}

__global__ void cnt_kernel(const int* __restrict__ a_lens,
                           const int* __restrict__ b_lens) {
    __shared__ int sh[256];
    int t = threadIdx.x;
    sh[t] = a_lens[t];
    __syncthreads();
    for (int o = 128; o; o >>= 1) { if (t < o) sh[t] += sh[t + o]; __syncthreads(); }
    if (t == 0) g_cnt[0] = (float)sh[0];
    __syncthreads();
    sh[t] = b_lens[t];
    __syncthreads();
    for (int o = 128; o; o >>= 1) { if (t < o) sh[t] += sh[t + o]; __syncthreads(); }
    if (t == 0) g_cnt[1] = (float)sh[0];
}

// Pad rows of length Ksrc to KPAD (zero fill). One block per row.
__global__ void pad_kernel(const float* __restrict__ src, float* __restrict__ dst,
                           int Ksrc) {
    size_t r = blockIdx.x;
    for (int k = threadIdx.x; k < KPAD; k += blockDim.x)
        dst[r * KPAD + k] = (k < Ksrc) ? src[r * Ksrc + k] : 0.0f;
}

// ---------------------------------------------------------------------------
// Tensor-core GEMM v3 (tf32 split, cp.async double buffer, fused masked
// BN statistics):  C[M,N] = X[M,K] @ W[N,K]^T + bias
//   also: sumOut[c] += sum over valid rows of C, sqOut[c] += sum of C^2
//   row r valid iff (r & (L-1)) < lens[r >> Lshift]   (L = 1<<Lshift)
// Requirements: M%128==0, N%128==0, K%16==0, rows 16B-aligned.
// 256 threads = 8 warps (2m x 4n), warp tile 64x32.
// ---------------------------------------------------------------------------
#define TBM 128
#define TBN 128
#define TBK 16
#define TST 20   // smem row stride (words)

__global__ __launch_bounds__(256)
void gemm_tc(const float* __restrict__ X, const float* __restrict__ W,
             const float* __restrict__ bias, float* __restrict__ C,
             int M, int N, int K,
             const int* __restrict__ lens, int Lshift,
             float* __restrict__ sumOut, float* __restrict__ sqOut) {
    __shared__ float Xs[2][TBM][TST];
    __shared__ float Ws[2][TBN][TST];

    int tid  = threadIdx.x;
    int warp = tid >> 5, lane = tid & 31;
    int wm = warp >> 2;          // 0..1
    int wn = warp & 3;           // 0..3
    int g  = lane >> 2, tig = lane & 3;
    size_t row0 = (size_t)blockIdx.y * TBM;
    int    col0 = blockIdx.x * TBN;

    float c[4][4][4];
#pragma unroll
    for (int mt = 0; mt < 4; mt++)
#pragma unroll
        for (int nt = 0; nt < 4; nt++)
#pragma unroll
            for (int i = 0; i < 4; i++) c[mt][nt][i] = 0.0f;

    int xr = tid >> 1;           // 0..127
    int xk = (tid & 1) * 8;      // 0 or 8

    const float* Xp = X + (row0 + xr) * (size_t)K + xk;
    const float* Wp = W + (size_t)(col0 + xr) * K + xk;

    uint32_t sx0 = (uint32_t)__cvta_generic_to_shared(&Xs[0][xr][xk]);
    uint32_t sx1 = (uint32_t)__cvta_generic_to_shared(&Xs[1][xr][xk]);
    uint32_t sw0 = (uint32_t)__cvta_generic_to_shared(&Ws[0][xr][xk]);
    uint32_t sw1 = (uint32_t)__cvta_generic_to_shared(&Ws[1][xr][xk]);

    int nk = K / TBK;

    // prologue: stage tile 0 into buf 0
    CP_ASYNC16(sx0,      Xp);
    CP_ASYNC16(sx0 + 16, Xp + 4);
    CP_ASYNC16(sw0,      Wp);
    CP_ASYNC16(sw0 + 16, Wp + 4);
    CP_COMMIT();

    for (int i = 0; i < nk; i++) {
        int buf = i & 1;
        if (i + 1 < nk) {
            const float* xp = Xp + (size_t)(i + 1) * TBK;
            const float* wp = Wp + (size_t)(i + 1) * TBK;
            uint32_t dx = buf ? sx0 : sx1;
            uint32_t dw = buf ? sw0 : sw1;
            CP_ASYNC16(dx,      xp);
            CP_ASYNC16(dx + 16, xp + 4);
            CP_ASYNC16(dw,      wp);
            CP_ASYNC16(dw + 16, wp + 4);
            CP_COMMIT();
            CP_WAIT1();
        } else {
            CP_WAIT0();
        }
        __syncthreads();

#pragma unroll
        for (int ks = 0; ks < 2; ks++) {
            int kb = ks * 8;
            uint32_t ah[4][4], al[4][4];
#pragma unroll
            for (int mt = 0; mt < 4; mt++) {
                int r = wm * 64 + mt * 16 + g;
                splitf(Xs[buf][r][kb + tig],          ah[mt][0], al[mt][0]);
                splitf(Xs[buf][r + 8][kb + tig],      ah[mt][1], al[mt][1]);
                splitf(Xs[buf][r][kb + tig + 4],      ah[mt][2], al[mt][2]);
                splitf(Xs[buf][r + 8][kb + tig + 4],  ah[mt][3], al[mt][3]);
            }
#pragma unroll
            for (int nt = 0; nt < 4; nt++) {
                int n = wn * 32 + nt * 8 + g;
                uint32_t bh[2], bl[2];
                splitf(Ws[buf][n][kb + tig],     bh[0], bl[0]);
                splitf(Ws[buf][n][kb + tig + 4], bh[1], bl[1]);
#pragma unroll
                for (int mt = 0; mt < 4; mt++) {
                    MMA_TF32(c[mt][nt], ah[mt], bh);   // hi*hi
                    MMA_TF32(c[mt][nt], ah[mt], bl);   // hi*lo
                    MMA_TF32(c[mt][nt], al[mt], bh);   // lo*hi
                }
            }
        }
        __syncthreads();
    }

    // --- epilogue: += bias, write C, accumulate masked column stats ---
    int Lm1 = (1 << Lshift) - 1;
    float ssum[4][2], ssq[4][2];
#pragma unroll
    for (int nt = 0; nt < 4; nt++) {
        ssum[nt][0] = ssum[nt][1] = 0.0f;
        ssq[nt][0]  = ssq[nt][1]  = 0.0f;
    }

#pragma unroll
    for (int mt = 0; mt < 4; mt++) {
        size_t r0 = row0 + wm * 64 + mt * 16 + g;
        size_t r1 = r0 + 8;
        bool v0 = ((int)(r0 & Lm1)) < lens[r0 >> Lshift];
        bool v1 = ((int)(r1 & Lm1)) < lens[r1 >> Lshift];
#pragma unroll
        for (int nt = 0; nt < 4; nt++) {
            int cc = col0 + wn * 32 + nt * 8 + tig * 2;
            float b0 = bias[cc], b1 = bias[cc + 1];
            float y00 = c[mt][nt][0] + b0;
            float y01 = c[mt][nt][1] + b1;
            float y10 = c[mt][nt][2] + b0;
            float y11 = c[mt][nt][3] + b1;
            C[r0 * N + cc]     = y00;
            C[r0 * N + cc + 1] = y01;
            C[r1 * N + cc]     = y10;
            C[r1 * N + cc + 1] = y11;
            if (v0) {
                ssum[nt][0] += y00; ssq[nt][0] += y00 * y00;
                ssum[nt][1] += y01; ssq[nt][1] += y01 * y01;
            }
            if (v1) {
                ssum[nt][0] += y10; ssq[nt][0] += y10 * y10;
                ssum[nt][1] += y11; ssq[nt][1] += y11 * y11;
            }
        }
    }

    // reduce over g-lanes (same column within warp), then atomics from 4 lanes
#pragma unroll
    for (int o = 16; o >= 4; o >>= 1) {
#pragma unroll
        for (int nt = 0; nt < 4; nt++) {
#pragma unroll
            for (int j = 0; j < 2; j++) {
                ssum[nt][j] += __shfl_xor_sync(0xffffffffu, ssum[nt][j], o);
                ssq[nt][j]  += __shfl_xor_sync(0xffffffffu, ssq[nt][j],  o);
            }
        }
    }
    if (g == 0) {
#pragma unroll
        for (int nt = 0; nt < 4; nt++) {
            int cc = col0 + wn * 32 + nt * 8 + tig * 2;
#pragma unroll
            for (int j = 0; j < 2; j++) {
                atomicAdd(&sumOut[cc + j], ssum[nt][j]);
                atomicAdd(&sqOut[cc + j],  ssq[nt][j]);
            }
        }
    }
}

// ---------------------------------------------------------------------------
// Tensor-core attention: one block per (s, 64-row q tile). 512 threads,
// 16 warps = 2m x 8n, warp tile 32x64. tf32 split everywhere.
// ---------------------------------------------------------------------------
#define AST 516   // scores stride: conflict-free A-frag loads
#define KST 20    // K / V^T chunk stride
#define ATT_SMEM_FLOATS (64 * AST + 512 * KST + 64 * KST)
#define ATT_SMEM_BYTES  (ATT_SMEM_FLOATS * 4)

__global__ __launch_bounds__(512)
void attention_tc(const float* __restrict__ q, const float* __restrict__ k,
                  const float* __restrict__ v, const int* __restrict__ b_lens,
                  float* __restrict__ wv) {
    extern __shared__ float sm[];
    float* sS = sm;                    // [64][AST]
    float* sK = sm + 64 * AST;         // [512][KST]
    float* sQ = sK + 512 * KST;        // [64][KST]

    int s   = blockIdx.x;
    int a0  = blockIdx.y * 64;
    int tid = threadIdx.x;
    int warp = tid >> 5, lane = tid & 31;
    int wm = warp >> 3;                // 0..1
    int wn = warp & 7;                 // 0..7
    int g  = lane >> 2, tig = lane & 3;
    int nb = b_lens[s];

    const float* qs = q + ((size_t)s * LA_ + a0) * DQK_;
    const float* ks = k + (size_t)s * LB_ * DQK_;
    const float* vs = v + (size_t)s * LB_ * DV_;

    float c[2][8][4];
#pragma unroll
    for (int mt = 0; mt < 2; mt++)
#pragma unroll
        for (int nt = 0; nt < 8; nt++)
#pragma unroll
            for (int i = 0; i < 4; i++) c[mt][nt][i] = 0.0f;

    // ---------------- Phase A: S = Q K^T ----------------
    for (int d0 = 0; d0 < DQK_; d0 += 16) {
        {   // Q tile 64x16
            int idx = tid * 2;
            int r = idx >> 4, cc = idx & 15;
            *reinterpret_cast<float2*>(&sQ[r * KST + cc]) =
                *reinterpret_cast<const float2*>(&qs[(size_t)r * DQK_ + d0 + cc]);
        }
#pragma unroll
        for (int i = 0; i < 4; i++) {
            int idx = tid + 512 * i;
            int b = idx >> 2, c4 = (idx & 3) * 4;
            *reinterpret_cast<float4*>(&sK[b * KST + c4]) =
                *reinterpret_cast<const float4*>(&ks[(size_t)b * DQK_ + d0 + c4]);
        }
        __syncthreads();

#pragma unroll
        for (int ks8 = 0; ks8 < 2; ks8++) {
            int kb = ks8 * 8;
            uint32_t ah[2][4], al[2][4];
#pragma unroll
            for (int mt = 0; mt < 2; mt++) {
                int r = wm * 32 + mt * 16 + g;
                splitf(sQ[r * KST + kb + tig],           ah[mt][0], al[mt][0]);
                splitf(sQ[(r + 8) * KST + kb + tig],     ah[mt][1], al[mt][1]);
                splitf(sQ[r * KST + kb + tig + 4],       ah[mt][2], al[mt][2]);
                splitf(sQ[(r + 8) * KST + kb + tig + 4], ah[mt][3], al[mt][3]);
            }
#pragma unroll
            for (int nt = 0; nt < 8; nt++) {
                int n = wn * 64 + nt * 8 + g;
                uint32_t bh[2], bl[2];
                splitf(sK[n * KST + kb + tig],     bh[0], bl[0]);
                splitf(sK[n * KST + kb + tig + 4], bh[1], bl[1]);
#pragma unroll
                for (int mt = 0; mt < 2; mt++) {
                    MMA_TF32(c[mt][nt], ah[mt], bh);
                    MMA_TF32(c[mt][nt], ah[mt], bl);
                    MMA_TF32(c[mt][nt], al[mt], bh);
                }
            }
        }
        __syncthreads();
    }

    const float scaler = 6.25f;
#pragma unroll
    for (int mt = 0; mt < 2; mt++) {
        int r = wm * 32 + mt * 16 + g;
#pragma unroll
        for (int nt = 0; nt < 8; nt++) {
            int col = wn * 64 + nt * 8 + tig * 2;
            float v0 = c[mt][nt][0] * scaler;
            float v1 = c[mt][nt][1] * scaler;
            float v2 = c[mt][nt][2] * scaler;
            float v3 = c[mt][nt][3] * scaler;
            sS[r * AST + col]           = (col     < nb) ? v0 : -1e30f;
            sS[r * AST + col + 1]       = (col + 1 < nb) ? v1 : -1e30f;
            sS[(r + 8) * AST + col]     = (col     < nb) ? v2 : -1e30f;
            sS[(r + 8) * AST + col + 1] = (col + 1 < nb) ? v3 : -1e30f;
        }
    }
    __syncthreads();

    // softmax: warp per 4 rows
#pragma unroll
    for (int rr = 0; rr < 4; rr++) {
        int row = warp * 4 + rr;
        float m = -1e30f;
        for (int cc = lane; cc < 512; cc += 32) m = fmaxf(m, sS[row * AST + cc]);
#pragma unroll
        for (int o = 16; o; o >>= 1) m = fmaxf(m, __shfl_xor_sync(0xffffffffu, m, o));
        float sum = 0.0f;
        for (int cc = lane; cc < 512; cc += 32) {
            float e = expf(sS[row * AST + cc] - m);
            sS[row * AST + cc] = e;
            sum += e;
        }
#pragma unroll
        for (int o = 16; o; o >>= 1) sum += __shfl_xor_sync(0xffffffffu, sum, o);
        float invs = 1.0f / sum;
        for (int cc = lane; cc < 512; cc += 32) sS[row * AST + cc] *= invs;
    }
    __syncthreads();

    // ---------------- Phase B: WV = P V ----------------
#pragma unroll
    for (int mt = 0; mt < 2; mt++)
#pragma unroll
        for (int nt = 0; nt < 8; nt++)
#pragma unroll
            for (int i = 0; i < 4; i++) c[mt][nt][i] = 0.0f;

    for (int b0 = 0; b0 < LB_; b0 += 16) {
#pragma unroll
        for (int i = 0; i < 4; i++) {
            int idx = tid + 512 * i;
            int kk = idx & 15, dg = idx >> 4;
            float4 vv = *reinterpret_cast<const float4*>(
                &vs[(size_t)(b0 + kk) * DV_ + dg * 4]);
            sK[(dg * 4 + 0) * KST + kk] = vv.x;
            sK[(dg * 4 + 1) * KST + kk] = vv.y;
            sK[(dg * 4 + 2) * KST + kk] = vv.z;
            sK[(dg * 4 + 3) * KST + kk] = vv.w;
        }
        __syncthreads();

#pragma unroll
        for (int ks8 = 0; ks8 < 2; ks8++) {
            int kb = ks8 * 8;
            uint32_t ah[2][4], al[2][4];
#pragma unroll
            for (int mt = 0; mt < 2; mt++) {
                int r = wm * 32 + mt * 16 + g;
                splitf(sS[r * AST + b0 + kb + tig],           ah[mt][0], al[mt][0]);
                splitf(sS[(r + 8) * AST + b0 + kb + tig],     ah[mt][1], al[mt][1]);
                splitf(sS[r * AST + b0 + kb + tig + 4],       ah[mt][2], al[mt][2]);
                splitf(sS[(r + 8) * AST + b0 + kb + tig + 4], ah[mt][3], al[mt][3]);
            }
#pragma unroll
            for (int nt = 0; nt < 8; nt++) {
                int n = wn * 64 + nt * 8 + g;
                uint32_t bh[2], bl[2];
                splitf(sK[n * KST + kb + tig],     bh[0], bl[0]);
                splitf(sK[n * KST + kb + tig + 4], bh[1], bl[1]);
#pragma unroll
                for (int mt = 0; mt < 2; mt++) {
                    MMA_TF32(c[mt][nt], ah[mt], bh);
                    MMA_TF32(c[mt][nt], ah[mt], bl);
                    MMA_TF32(c[mt][nt], al[mt], bh);
                }
            }
        }
        __syncthreads();
    }

    float* wvp = wv + ((size_t)s * LA_ + a0) * DV_;
#pragma unroll
    for (int mt = 0; mt < 2; mt++) {
        int r = wm * 32 + mt * 16 + g;
#pragma unroll
        for (int nt = 0; nt < 8; nt++) {
            int col = wn * 64 + nt * 8 + tig * 2;
            wvp[(size_t)r * DV_ + col]           = c[mt][nt][0];
            wvp[(size_t)r * DV_ + col + 1]       = c[mt][nt][1];
            wvp[(size_t)(r + 8) * DV_ + col]     = c[mt][nt][2];
            wvp[(size_t)(r + 8) * DV_ + col + 1] = c[mt][nt][3];
        }
    }
}

// ---------------------------------------------------------------------------
// BN apply + ReLU + optional L2 row-normalize + optional row mask.
// ---------------------------------------------------------------------------
__global__ __launch_bounds__(128)
void bn_apply_kernel(float* __restrict__ Y, int D,
                     const float* __restrict__ ssum, const float* __restrict__ ssq,
                     const float* __restrict__ cntp,
                     const float* __restrict__ gamma, const float* __restrict__ beta,
                     const int* __restrict__ lens, int L,
                     int normalize, int maskOut, float* __restrict__ out) {
    int r = blockIdx.x;
    int sidx = r / L;
    int l    = r - sidx * L;
    bool valid = (l < lens[sidx]);

    float inv = 1.0f / (*cntp);
    int t = threadIdx.x;
    int per = D >> 7;

    float vals[4];
    float ss = 0.0f;
#pragma unroll 4
    for (int i = 0; i < per; i++) {
        int cc = t + (i << 7);
        float mean = ssum[cc] * inv;
        float var  = ssq[cc] * inv - mean * mean;
        var = fmaxf(var, 0.0f);
        float z = (Y[(size_t)r * D + cc] - mean) * rsqrtf(var + 1e-5f) * gamma[cc] + beta[cc];
        z = fmaxf(z, 0.0f);
        vals[i] = z;
        ss += z * z;
    }

    __shared__ float red[4];
#pragma unroll
    for (int o = 16; o; o >>= 1) ss += __shfl_xor_sync(0xffffffffu, ss, o);
    if ((t & 31) == 0) red[t >> 5] = ss;
    __syncthreads();
    float tot = red[0] + red[1] + red[2] + red[3];

    float scale = 1.0f;
    if (normalize) scale = 1.0f / fmaxf(sqrtf(tot), 1e-12f);
    if (maskOut && !valid) scale = 0.0f;

    float* dst = out ? out : Y;
#pragma unroll 4
    for (int i = 0; i < per; i++) {
        int cc = t + (i << 7);
        dst[(size_t)r * D + cc] = vals[i] * scale;
    }
}

// ---------------------------------------------------------------------------
// Launch
// ---------------------------------------------------------------------------
extern "C" void kernel_launch(void* const* d_in, const int* in_sizes, int n_in,
                              void* d_out, int out_size) {
    const float* A      = (const float*)d_in[0];
    const float* B      = (const float*)d_in[1];
    const int*   a_lens = (const int*)  d_in[2];
    const int*   b_lens = (const int*)  d_in[3];
    const float* Wq     = (const float*)d_in[4];
    const float* bq     = (const float*)d_in[5];
    const float* gq     = (const float*)d_in[6];
    const float* betaq  = (const float*)d_in[7];
    const float* Wk     = (const float*)d_in[8];
    const float* bk     = (const float*)d_in[9];
    const float* gk     = (const float*)d_in[10];
    const float* betak  = (const float*)d_in[11];
    const float* Wv     = (const float*)d_in[12];
    const float* bv     = (const float*)d_in[13];
    const float* gv     = (const float*)d_in[14];
    const float* betav  = (const float*)d_in[15];
    const float* Wf     = (const float*)d_in[16];
    const float* bf     = (const float*)d_in[17];
    const float* gf     = (const float*)d_in[18];
    const float* betaf  = (const float*)d_in[19];
    float* out = (float*)d_out;

    float *Yq, *Yk, *Yv, *Ywv, *Yf, *Bp, *Wkp, *Wvp, *stats, *cnt;
    cudaGetSymbolAddress((void**)&Yq,   g_Yq);
    cudaGetSymbolAddress((void**)&Yk,   g_Yk);
    cudaGetSymbolAddress((void**)&Yv,   g_Yv);
    cudaGetSymbolAddress((void**)&Ywv,  g_Ywv);
    cudaGetSymbolAddress((void**)&Yf,   g_Yf);
    cudaGetSymbolAddress((void**)&Bp,   g_Bp);
    cudaGetSymbolAddress((void**)&Wkp,  g_Wkp);
    cudaGetSymbolAddress((void**)&Wvp,  g_Wvp);
    cudaGetSymbolAddress((void**)&stats, g_stats);
    cudaGetSymbolAddress((void**)&cnt,  g_cnt);

    cudaFuncSetAttribute(attention_tc,
                         cudaFuncAttributeMaxDynamicSharedMemorySize, ATT_SMEM_BYTES);

    float* sum_q = stats + 0 * 512;
    float* sq_q  = stats + 1 * 512;
    float* sum_k = stats + 2 * 512;
    float* sq_k  = stats + 3 * 512;
    float* sum_v = stats + 4 * 512;
    float* sq_v  = stats + 5 * 512;
    float* sum_f = stats + 6 * 512;
    float* sq_f  = stats + 7 * 512;

    // 0) reset accumulators + pad odd-K operands
    zero_stats_kernel<<<16, 256>>>();
    cnt_kernel<<<1, 256>>>(a_lens, b_lens);
    pad_kernel<<<ROWS_B, 256>>>(B,  Bp,  DKV_);
    pad_kernel<<<512, 256>>>(Wk, Wkp, DKV_);
    pad_kernel<<<512, 256>>>(Wv, Wvp, DKV_);

    // 1) projection GEMMs with fused masked stats (Lshift: 7 for La, 9 for Lb)
    gemm_tc<<<dim3(DQK_ / TBN, ROWS_A / TBM), 256>>>(A,  Wq,  bq, Yq, ROWS_A, DQK_, DQ_,
                                                     a_lens, 7, sum_q, sq_q);
    gemm_tc<<<dim3(DQK_ / TBN, ROWS_B / TBM), 256>>>(Bp, Wkp, bk, Yk, ROWS_B, DQK_, KPAD,
                                                     b_lens, 9, sum_k, sq_k);
    gemm_tc<<<dim3(DV_  / TBN, ROWS_B / TBM), 256>>>(Bp, Wvp, bv, Yv, ROWS_B, DV_,  KPAD,
                                                     b_lens, 9, sum_v, sq_v);

    // 2) BN + ReLU + L2-normalize (in-place)
    bn_apply_kernel<<<ROWS_A, 128>>>(Yq, DQK_, sum_q, sq_q, cnt + 0, gq, betaq, a_lens, LA_, 1, 0, nullptr);
    bn_apply_kernel<<<ROWS_B, 128>>>(Yk, DQK_, sum_k, sq_k, cnt + 1, gk, betak, b_lens, LB_, 1, 0, nullptr);
    bn_apply_kernel<<<ROWS_B, 128>>>(Yv, DV_,  sum_v, sq_v, cnt + 1, gv, betav, b_lens, LB_, 1, 0, nullptr);

    // 3) attention (tensor core)
    attention_tc<<<dim3(S_, LA_ / 64), 512, ATT_SMEM_BYTES>>>(Yq, Yk, Yv, b_lens, Ywv);

    // 4) final projection (fused stats) + BN + ReLU + output mask
    gemm_tc<<<dim3(DQ_ / TBN, ROWS_A / TBM), 256>>>(Ywv, Wf, bf, Yf, ROWS_A, DQ_, DV_,
                                                    a_lens, 7, sum_f, sq_f);
    bn_apply_kernel<<<ROWS_A, 128>>>(Yf, DQ_, sum_f, sq_f, cnt + 0, gf, betaf, a_lens, LA_, 0, 1, out);
}

// round 5
// speedup vs baseline: 2.5599x; 1.3740x over previous
#include <cuda_runtime.h>
#include <cuda_bf16.h>
#include <math.h>
#include <stdint.h>

// ---------------------------------------------------------------------------
// Problem constants
// ---------------------------------------------------------------------------
#define S_   256
#define LA_  128
#define LB_  512
#define DQ_  256
#define DKV_ 265
#define DQK_ 512
#define DV_  512
#define KPAD 272            // DKV_ padded to multiple of 16

#define ROWS_A (S_ * LA_)   // 32768
#define ROWS_B (S_ * LB_)   // 131072

// Scratch (device globals; no allocation allowed)
__device__ float g_Yq [(size_t)ROWS_A * DQK_];
__device__ float g_Yk [(size_t)ROWS_B * DQK_];
__device__ float g_Yv [(size_t)ROWS_B * DV_];
__device__ float g_Ywv[(size_t)ROWS_A * DV_];
__device__ float g_Yf [(size_t)ROWS_A * DQ_];
__device__ float g_Bp [(size_t)ROWS_B * KPAD];   // padded B
__device__ float g_Wkp[512 * KPAD];
__device__ float g_Wvp[512 * KPAD];
__device__ float g_stats[8 * 512];
__device__ float g_cnt[2];

// ---------------------------------------------------------------------------
// Helpers: bf16 2-term split + bf16 mma + cp.async
// ---------------------------------------------------------------------------
// Pack (x0, x1) -> hi bf16x2 (lower half = x0) and lo bf16x2 (residuals).
__device__ __forceinline__ void split2(float x0, float x1, uint32_t& h, uint32_t& l) {
    uint32_t hp;
    asm("cvt.rn.bf16x2.f32 %0, %1, %2;" : "=r"(hp) : "f"(x1), "f"(x0));
    float h0 = __uint_as_float(hp << 16);
    float h1 = __uint_as_float(hp & 0xffff0000u);
    asm("cvt.rn.bf16x2.f32 %0, %1, %2;" : "=r"(l) : "f"(x1 - h1), "f"(x0 - h0));
    h = hp;
}

#define MMA_BF16(c, a, b)                                                  \
  asm volatile("mma.sync.aligned.m16n8k16.row.col.f32.bf16.bf16.f32 "      \
    "{%0,%1,%2,%3}, {%4,%5,%6,%7}, {%8,%9}, {%0,%1,%2,%3};"                \
    : "+f"(c[0]), "+f"(c[1]), "+f"(c[2]), "+f"(c[3])                       \
    : "r"(a[0]), "r"(a[1]), "r"(a[2]), "r"(a[3]), "r"(b[0]), "r"(b[1]))

#define CP_ASYNC16(smem_u32, gptr) \
  asm volatile("cp.async.cg.shared.global [%0], [%1], 16;" :: "r"(smem_u32), "l"(gptr))
#define CP_COMMIT() asm volatile("cp.async.commit_group;")
#define CP_WAIT1()  asm volatile("cp.async.wait_group 1;")
#define CP_WAIT0()  asm volatile("cp.async.wait_group 0;")

// ---------------------------------------------------------------------------
// Small init kernels
// ---------------------------------------------------------------------------
__global__ void zero_stats_kernel() {
    int i = blockIdx.x * blockDim.x + threadIdx.x;
    if (i < 8 * 512) g_stats[i] = 0.0f;
}

__global__ void cnt_kernel(const int* __restrict__ a_lens,
                           const int* __restrict__ b_lens) {
    __shared__ int sh[256];
    int t = threadIdx.x;
    sh[t] = a_lens[t];
    __syncthreads();
    for (int o = 128; o; o >>= 1) { if (t < o) sh[t] += sh[t + o]; __syncthreads(); }
    if (t == 0) g_cnt[0] = (float)sh[0];
    __syncthreads();
    sh[t] = b_lens[t];
    __syncthreads();
    for (int o = 128; o; o >>= 1) { if (t < o) sh[t] += sh[t + o]; __syncthreads(); }
    if (t == 0) g_cnt[1] = (float)sh[0];
}

// Pad rows of length Ksrc to KPAD (zero fill). One block per row.
__global__ void pad_kernel(const float* __restrict__ src, float* __restrict__ dst,
                           int Ksrc) {
    size_t r = blockIdx.x;
    for (int k = threadIdx.x; k < KPAD; k += blockDim.x)
        dst[r * KPAD + k] = (k < Ksrc) ? src[r * Ksrc + k] : 0.0f;
}

// ---------------------------------------------------------------------------
// Tensor-core GEMM v4 (bf16 2-term split, m16n8k16, cp.async double buffer,
// fused masked BN statistics):  C[M,N] = X[M,K] @ W[N,K]^T + bias
// 256 threads = 8 warps (2m x 4n), warp tile 64x32. K%16==0.
// ---------------------------------------------------------------------------
#define TBM 128
#define TBN 128
#define TBK 16
#define TST 24   // smem row stride (words): conflict-free float2 frag loads

__global__ __launch_bounds__(256)
void gemm_tc(const float* __restrict__ X, const float* __restrict__ W,
             const float* __restrict__ bias, float* __restrict__ C,
             int M, int N, int K,
             const int* __restrict__ lens, int Lshift,
             float* __restrict__ sumOut, float* __restrict__ sqOut) {
    __shared__ float Xs[2][TBM][TST];
    __shared__ float Ws[2][TBN][TST];

    int tid  = threadIdx.x;
    int warp = tid >> 5, lane = tid & 31;
    int wm = warp >> 2;          // 0..1
    int wn = warp & 3;           // 0..3
    int g  = lane >> 2, tig = lane & 3;
    size_t row0 = (size_t)blockIdx.y * TBM;
    int    col0 = blockIdx.x * TBN;

    float c[4][4][4];
#pragma unroll
    for (int mt = 0; mt < 4; mt++)
#pragma unroll
        for (int nt = 0; nt < 4; nt++)
#pragma unroll
            for (int i = 0; i < 4; i++) c[mt][nt][i] = 0.0f;

    int xr = tid >> 1;           // 0..127
    int xk = (tid & 1) * 8;      // 0 or 8

    const float* Xp = X + (row0 + xr) * (size_t)K + xk;
    const float* Wp = W + (size_t)(col0 + xr) * K + xk;

    uint32_t sx0 = (uint32_t)__cvta_generic_to_shared(&Xs[0][xr][xk]);
    uint32_t sx1 = (uint32_t)__cvta_generic_to_shared(&Xs[1][xr][xk]);
    uint32_t sw0 = (uint32_t)__cvta_generic_to_shared(&Ws[0][xr][xk]);
    uint32_t sw1 = (uint32_t)__cvta_generic_to_shared(&Ws[1][xr][xk]);

    int nk = K / TBK;

    // prologue
    CP_ASYNC16(sx0,      Xp);
    CP_ASYNC16(sx0 + 16, Xp + 4);
    CP_ASYNC16(sw0,      Wp);
    CP_ASYNC16(sw0 + 16, Wp + 4);
    CP_COMMIT();

    for (int i = 0; i < nk; i++) {
        int buf = i & 1;
        if (i + 1 < nk) {
            const float* xp = Xp + (size_t)(i + 1) * TBK;
            const float* wp = Wp + (size_t)(i + 1) * TBK;
            uint32_t dx = buf ? sx0 : sx1;
            uint32_t dw = buf ? sw0 : sw1;
            CP_ASYNC16(dx,      xp);
            CP_ASYNC16(dx + 16, xp + 4);
            CP_ASYNC16(dw,      wp);
            CP_ASYNC16(dw + 16, wp + 4);
            CP_COMMIT();
            CP_WAIT1();
        } else {
            CP_WAIT0();
        }
        __syncthreads();

        uint32_t ah[4][4], al[4][4];
#pragma unroll
        for (int mt = 0; mt < 4; mt++) {
            int r = wm * 64 + mt * 16 + g;
            float2 p0 = *reinterpret_cast<const float2*>(&Xs[buf][r][2 * tig]);
            float2 p1 = *reinterpret_cast<const float2*>(&Xs[buf][r + 8][2 * tig]);
            float2 p2 = *reinterpret_cast<const float2*>(&Xs[buf][r][2 * tig + 8]);
            float2 p3 = *reinterpret_cast<const float2*>(&Xs[buf][r + 8][2 * tig + 8]);
            split2(p0.x, p0.y, ah[mt][0], al[mt][0]);
            split2(p1.x, p1.y, ah[mt][1], al[mt][1]);
            split2(p2.x, p2.y, ah[mt][2], al[mt][2]);
            split2(p3.x, p3.y, ah[mt][3], al[mt][3]);
        }
#pragma unroll
        for (int nt = 0; nt < 4; nt++) {
            int n = wn * 32 + nt * 8 + g;
            float2 q0 = *reinterpret_cast<const float2*>(&Ws[buf][n][2 * tig]);
            float2 q1 = *reinterpret_cast<const float2*>(&Ws[buf][n][2 * tig + 8]);
            uint32_t bh[2], bl[2];
            split2(q0.x, q0.y, bh[0], bl[0]);
            split2(q1.x, q1.y, bh[1], bl[1]);
#pragma unroll
            for (int mt = 0; mt < 4; mt++) {
                MMA_BF16(c[mt][nt], ah[mt], bh);   // hi*hi
                MMA_BF16(c[mt][nt], ah[mt], bl);   // hi*lo
                MMA_BF16(c[mt][nt], al[mt], bh);   // lo*hi
            }
        }
        __syncthreads();
    }

    // --- epilogue: += bias, write C, accumulate masked column stats ---
    int Lm1 = (1 << Lshift) - 1;
    float ssum[4][2], ssq[4][2];
#pragma unroll
    for (int nt = 0; nt < 4; nt++) {
        ssum[nt][0] = ssum[nt][1] = 0.0f;
        ssq[nt][0]  = ssq[nt][1]  = 0.0f;
    }

#pragma unroll
    for (int mt = 0; mt < 4; mt++) {
        size_t r0 = row0 + wm * 64 + mt * 16 + g;
        size_t r1 = r0 + 8;
        bool v0 = ((int)(r0 & Lm1)) < lens[r0 >> Lshift];
        bool v1 = ((int)(r1 & Lm1)) < lens[r1 >> Lshift];
#pragma unroll
        for (int nt = 0; nt < 4; nt++) {
            int cc = col0 + wn * 32 + nt * 8 + tig * 2;
            float b0 = bias[cc], b1 = bias[cc + 1];
            float y00 = c[mt][nt][0] + b0;
            float y01 = c[mt][nt][1] + b1;
            float y10 = c[mt][nt][2] + b0;
            float y11 = c[mt][nt][3] + b1;
            C[r0 * N + cc]     = y00;
            C[r0 * N + cc + 1] = y01;
            C[r1 * N + cc]     = y10;
            C[r1 * N + cc + 1] = y11;
            if (v0) {
                ssum[nt][0] += y00; ssq[nt][0] += y00 * y00;
                ssum[nt][1] += y01; ssq[nt][1] += y01 * y01;
            }
            if (v1) {
                ssum[nt][0] += y10; ssq[nt][0] += y10 * y10;
                ssum[nt][1] += y11; ssq[nt][1] += y11 * y11;
            }
        }
    }

#pragma unroll
    for (int o = 16; o >= 4; o >>= 1) {
#pragma unroll
        for (int nt = 0; nt < 4; nt++) {
#pragma unroll
            for (int j = 0; j < 2; j++) {
                ssum[nt][j] += __shfl_xor_sync(0xffffffffu, ssum[nt][j], o);
                ssq[nt][j]  += __shfl_xor_sync(0xffffffffu, ssq[nt][j],  o);
            }
        }
    }
    if (g == 0) {
#pragma unroll
        for (int nt = 0; nt < 4; nt++) {
            int cc = col0 + wn * 32 + nt * 8 + tig * 2;
#pragma unroll
            for (int j = 0; j < 2; j++) {
                atomicAdd(&sumOut[cc + j], ssum[nt][j]);
                atomicAdd(&sqOut[cc + j],  ssq[nt][j]);
            }
        }
    }
}

// ---------------------------------------------------------------------------
// Tensor-core attention (bf16 split, m16n8k16): one block per (s, 64 q rows).
// 512 threads, 16 warps = 2m x 8n, warp tile 32x64.
// ---------------------------------------------------------------------------
#define AST 520   // scores stride: conflict-free float2 A-frag loads
#define KST 24    // K / V^T chunk stride
#define ATT_SMEM_FLOATS (64 * AST + 512 * KST + 64 * KST)
#define ATT_SMEM_BYTES  (ATT_SMEM_FLOATS * 4)   // 188416 B

__global__ __launch_bounds__(512)
void attention_tc(const float* __restrict__ q, const float* __restrict__ k,
                  const float* __restrict__ v, const int* __restrict__ b_lens,
                  float* __restrict__ wv) {
    extern __shared__ float sm[];
    float* sS = sm;                    // [64][AST]
    float* sK = sm + 64 * AST;         // [512][KST]
    float* sQ = sK + 512 * KST;        // [64][KST]

    int s   = blockIdx.x;
    int a0  = blockIdx.y * 64;
    int tid = threadIdx.x;
    int warp = tid >> 5, lane = tid & 31;
    int wm = warp >> 3;                // 0..1
    int wn = warp & 7;                 // 0..7
    int g  = lane >> 2, tig = lane & 3;
    int nb = b_lens[s];

    const float* qs = q + ((size_t)s * LA_ + a0) * DQK_;
    const float* ks = k + (size_t)s * LB_ * DQK_;
    const float* vs = v + (size_t)s * LB_ * DV_;

    float c[2][8][4];
#pragma unroll
    for (int mt = 0; mt < 2; mt++)
#pragma unroll
        for (int nt = 0; nt < 8; nt++)
#pragma unroll
            for (int i = 0; i < 4; i++) c[mt][nt][i] = 0.0f;

    // ---------------- Phase A: S = Q K^T ----------------
    for (int d0 = 0; d0 < DQK_; d0 += 16) {
        {   // Q tile 64x16
            int idx = tid * 2;
            int r = idx >> 4, cc = idx & 15;
            *reinterpret_cast<float2*>(&sQ[r * KST + cc]) =
                *reinterpret_cast<const float2*>(&qs[(size_t)r * DQK_ + d0 + cc]);
        }
#pragma unroll
        for (int i = 0; i < 4; i++) {
            int idx = tid + 512 * i;
            int b = idx >> 2, c4 = (idx & 3) * 4;
            *reinterpret_cast<float4*>(&sK[b * KST + c4]) =
                *reinterpret_cast<const float4*>(&ks[(size_t)b * DQK_ + d0 + c4]);
        }
        __syncthreads();

        uint32_t ah[2][4], al[2][4];
#pragma unroll
        for (int mt = 0; mt < 2; mt++) {
            int r = wm * 32 + mt * 16 + g;
            float2 p0 = *reinterpret_cast<const float2*>(&sQ[r * KST + 2 * tig]);
            float2 p1 = *reinterpret_cast<const float2*>(&sQ[(r + 8) * KST + 2 * tig]);
            float2 p2 = *reinterpret_cast<const float2*>(&sQ[r * KST + 2 * tig + 8]);
            float2 p3 = *reinterpret_cast<const float2*>(&sQ[(r + 8) * KST + 2 * tig + 8]);
            split2(p0.x, p0.y, ah[mt][0], al[mt][0]);
            split2(p1.x, p1.y, ah[mt][1], al[mt][1]);
            split2(p2.x, p2.y, ah[mt][2], al[mt][2]);
            split2(p3.x, p3.y, ah[mt][3], al[mt][3]);
        }
#pragma unroll
        for (int nt = 0; nt < 8; nt++) {
            int n = wn * 64 + nt * 8 + g;
            float2 q0 = *reinterpret_cast<const float2*>(&sK[n * KST + 2 * tig]);
            float2 q1 = *reinterpret_cast<const float2*>(&sK[n * KST + 2 * tig + 8]);
            uint32_t bh[2], bl[2];
            split2(q0.x, q0.y, bh[0], bl[0]);
            split2(q1.x, q1.y, bh[1], bl[1]);
#pragma unroll
            for (int mt = 0; mt < 2; mt++) {
                MMA_BF16(c[mt][nt], ah[mt], bh);
                MMA_BF16(c[mt][nt], ah[mt], bl);
                MMA_BF16(c[mt][nt], al[mt], bh);
            }
        }
        __syncthreads();
    }

    const float scaler = 6.25f;
#pragma unroll
    for (int mt = 0; mt < 2; mt++) {
        int r = wm * 32 + mt * 16 + g;
#pragma unroll
        for (int nt = 0; nt < 8; nt++) {
            int col = wn * 64 + nt * 8 + tig * 2;
            float v0 = c[mt][nt][0] * scaler;
            float v1 = c[mt][nt][1] * scaler;
            float v2 = c[mt][nt][2] * scaler;
            float v3 = c[mt][nt][3] * scaler;
            sS[r * AST + col]           = (col     < nb) ? v0 : -1e30f;
            sS[r * AST + col + 1]       = (col + 1 < nb) ? v1 : -1e30f;
            sS[(r + 8) * AST + col]     = (col     < nb) ? v2 : -1e30f;
            sS[(r + 8) * AST + col + 1] = (col + 1 < nb) ? v3 : -1e30f;
        }
    }
    __syncthreads();

    // softmax: warp per 4 rows
#pragma unroll
    for (int rr = 0; rr < 4; rr++) {
        int row = warp * 4 + rr;
        float m = -1e30f;
        for (int cc = lane; cc < 512; cc += 32) m = fmaxf(m, sS[row * AST + cc]);
#pragma unroll
        for (int o = 16; o; o >>= 1) m = fmaxf(m, __shfl_xor_sync(0xffffffffu, m, o));
        float sum = 0.0f;
        for (int cc = lane; cc < 512; cc += 32) {
            float e = expf(sS[row * AST + cc] - m);
            sS[row * AST + cc] = e;
            sum += e;
        }
#pragma unroll
        for (int o = 16; o; o >>= 1) sum += __shfl_xor_sync(0xffffffffu, sum, o);
        float invs = 1.0f / sum;
        for (int cc = lane; cc < 512; cc += 32) sS[row * AST + cc] *= invs;
    }
    __syncthreads();

    // ---------------- Phase B: WV = P V ----------------
#pragma unroll
    for (int mt = 0; mt < 2; mt++)
#pragma unroll
        for (int nt = 0; nt < 8; nt++)
#pragma unroll
            for (int i = 0; i < 4; i++) c[mt][nt][i] = 0.0f;

    for (int b0 = 0; b0 < LB_; b0 += 16) {
#pragma unroll
        for (int i = 0; i < 4; i++) {
            int idx = tid + 512 * i;
            int kk = idx & 15, dg = idx >> 4;
            float4 vv = *reinterpret_cast<const float4*>(
                &vs[(size_t)(b0 + kk) * DV_ + dg * 4]);
            sK[(dg * 4 + 0) * KST + kk] = vv.x;
            sK[(dg * 4 + 1) * KST + kk] = vv.y;
            sK[(dg * 4 + 2) * KST + kk] = vv.z;
            sK[(dg * 4 + 3) * KST + kk] = vv.w;
        }
        __syncthreads();

        uint32_t ah[2][4], al[2][4];
#pragma unroll
        for (int mt = 0; mt < 2; mt++) {
            int r = wm * 32 + mt * 16 + g;
            float2 p0 = *reinterpret_cast<const float2*>(&sS[r * AST + b0 + 2 * tig]);
            float2 p1 = *reinterpret_cast<const float2*>(&sS[(r + 8) * AST + b0 + 2 * tig]);
            float2 p2 = *reinterpret_cast<const float2*>(&sS[r * AST + b0 + 2 * tig + 8]);
            float2 p3 = *reinterpret_cast<const float2*>(&sS[(r + 8) * AST + b0 + 2 * tig + 8]);
            split2(p0.x, p0.y, ah[mt][0], al[mt][0]);
            split2(p1.x, p1.y, ah[mt][1], al[mt][1]);
            split2(p2.x, p2.y, ah[mt][2], al[mt][2]);
            split2(p3.x, p3.y, ah[mt][3], al[mt][3]);
        }
#pragma unroll
        for (int nt = 0; nt < 8; nt++) {
            int n = wn * 64 + nt * 8 + g;
            float2 q0 = *reinterpret_cast<const float2*>(&sK[n * KST + 2 * tig]);
            float2 q1 = *reinterpret_cast<const float2*>(&sK[n * KST + 2 * tig + 8]);
            uint32_t bh[2], bl[2];
            split2(q0.x, q0.y, bh[0], bl[0]);
            split2(q1.x, q1.y, bh[1], bl[1]);
#pragma unroll
            for (int mt = 0; mt < 2; mt++) {
                MMA_BF16(c[mt][nt], ah[mt], bh);
                MMA_BF16(c[mt][nt], ah[mt], bl);
                MMA_BF16(c[mt][nt], al[mt], bh);
            }
        }
        __syncthreads();
    }

    float* wvp = wv + ((size_t)s * LA_ + a0) * DV_;
#pragma unroll
    for (int mt = 0; mt < 2; mt++) {
        int r = wm * 32 + mt * 16 + g;
#pragma unroll
        for (int nt = 0; nt < 8; nt++) {
            int col = wn * 64 + nt * 8 + tig * 2;
            wvp[(size_t)r * DV_ + col]           = c[mt][nt][0];
            wvp[(size_t)r * DV_ + col + 1]       = c[mt][nt][1];
            wvp[(size_t)(r + 8) * DV_ + col]     = c[mt][nt][2];
            wvp[(size_t)(r + 8) * DV_ + col + 1] = c[mt][nt][3];
        }
    }
}

// ---------------------------------------------------------------------------
// BN apply + ReLU + optional L2 row-normalize + optional row mask.
// ---------------------------------------------------------------------------
__global__ __launch_bounds__(128)
void bn_apply_kernel(float* __restrict__ Y, int D,
                     const float* __restrict__ ssum, const float* __restrict__ ssq,
                     const float* __restrict__ cntp,
                     const float* __restrict__ gamma, const float* __restrict__ beta,
                     const int* __restrict__ lens, int L,
                     int normalize, int maskOut, float* __restrict__ out) {
    int r = blockIdx.x;
    int sidx = r / L;
    int l    = r - sidx * L;
    bool valid = (l < lens[sidx]);

    float inv = 1.0f / (*cntp);
    int t = threadIdx.x;
    int per = D >> 7;

    float vals[4];
    float ss = 0.0f;
#pragma unroll 4
    for (int i = 0; i < per; i++) {
        int cc = t + (i << 7);
        float mean = ssum[cc] * inv;
        float var  = ssq[cc] * inv - mean * mean;
        var = fmaxf(var, 0.0f);
        float z = (Y[(size_t)r * D + cc] - mean) * rsqrtf(var + 1e-5f) * gamma[cc] + beta[cc];
        z = fmaxf(z, 0.0f);
        vals[i] = z;
        ss += z * z;
    }

    __shared__ float red[4];
#pragma unroll
    for (int o = 16; o; o >>= 1) ss += __shfl_xor_sync(0xffffffffu, ss, o);
    if ((t & 31) == 0) red[t >> 5] = ss;
    __syncthreads();
    float tot = red[0] + red[1] + red[2] + red[3];

    float scale = 1.0f;
    if (normalize) scale = 1.0f / fmaxf(sqrtf(tot), 1e-12f);
    if (maskOut && !valid) scale = 0.0f;

    float* dst = out ? out : Y;
#pragma unroll 4
    for (int i = 0; i < per; i++) {
        int cc = t + (i << 7);
        dst[(size_t)r * D + cc] = vals[i] * scale;
    }
}

// ---------------------------------------------------------------------------
// Launch
// ---------------------------------------------------------------------------
extern "C" void kernel_launch(void* const* d_in, const int* in_sizes, int n_in,
                              void* d_out, int out_size) {
    const float* A      = (const float*)d_in[0];
    const float* B      = (const float*)d_in[1];
    const int*   a_lens = (const int*)  d_in[2];
    const int*   b_lens = (const int*)  d_in[3];
    const float* Wq     = (const float*)d_in[4];
    const float* bq     = (const float*)d_in[5];
    const float* gq     = (const float*)d_in[6];
    const float* betaq  = (const float*)d_in[7];
    const float* Wk     = (const float*)d_in[8];
    const float* bk     = (const float*)d_in[9];
    const float* gk     = (const float*)d_in[10];
    const float* betak  = (const float*)d_in[11];
    const float* Wv     = (const float*)d_in[12];
    const float* bv     = (const float*)d_in[13];
    const float* gv     = (const float*)d_in[14];
    const float* betav  = (const float*)d_in[15];
    const float* Wf     = (const float*)d_in[16];
    const float* bf     = (const float*)d_in[17];
    const float* gf     = (const float*)d_in[18];
    const float* betaf  = (const float*)d_in[19];
    float* out = (float*)d_out;

    float *Yq, *Yk, *Yv, *Ywv, *Yf, *Bp, *Wkp, *Wvp, *stats, *cnt;
    cudaGetSymbolAddress((void**)&Yq,   g_Yq);
    cudaGetSymbolAddress((void**)&Yk,   g_Yk);
    cudaGetSymbolAddress((void**)&Yv,   g_Yv);
    cudaGetSymbolAddress((void**)&Ywv,  g_Ywv);
    cudaGetSymbolAddress((void**)&Yf,   g_Yf);
    cudaGetSymbolAddress((void**)&Bp,   g_Bp);
    cudaGetSymbolAddress((void**)&Wkp,  g_Wkp);
    cudaGetSymbolAddress((void**)&Wvp,  g_Wvp);
    cudaGetSymbolAddress((void**)&stats, g_stats);
    cudaGetSymbolAddress((void**)&cnt,  g_cnt);

    cudaFuncSetAttribute(attention_tc,
                         cudaFuncAttributeMaxDynamicSharedMemorySize, ATT_SMEM_BYTES);

    float* sum_q = stats + 0 * 512;
    float* sq_q  = stats + 1 * 512;
    float* sum_k = stats + 2 * 512;
    float* sq_k  = stats + 3 * 512;
    float* sum_v = stats + 4 * 512;
    float* sq_v  = stats + 5 * 512;
    float* sum_f = stats + 6 * 512;
    float* sq_f  = stats + 7 * 512;

    // 0) reset accumulators + pad odd-K operands
    zero_stats_kernel<<<16, 256>>>();
    cnt_kernel<<<1, 256>>>(a_lens, b_lens);
    pad_kernel<<<ROWS_B, 256>>>(B,  Bp,  DKV_);
    pad_kernel<<<512, 256>>>(Wk, Wkp, DKV_);
    pad_kernel<<<512, 256>>>(Wv, Wvp, DKV_);

    // 1) projection GEMMs with fused masked stats (Lshift: 7 for La, 9 for Lb)
    gemm_tc<<<dim3(DQK_ / TBN, ROWS_A / TBM), 256>>>(A,  Wq,  bq, Yq, ROWS_A, DQK_, DQ_,
                                                     a_lens, 7, sum_q, sq_q);
    gemm_tc<<<dim3(DQK_ / TBN, ROWS_B / TBM), 256>>>(Bp, Wkp, bk, Yk, ROWS_B, DQK_, KPAD,
                                                     b_lens, 9, sum_k, sq_k);
    gemm_tc<<<dim3(DV_  / TBN, ROWS_B / TBM), 256>>>(Bp, Wvp, bv, Yv, ROWS_B, DV_,  KPAD,
                                                     b_lens, 9, sum_v, sq_v);

    // 2) BN + ReLU + L2-normalize (in-place)
    bn_apply_kernel<<<ROWS_A, 128>>>(Yq, DQK_, sum_q, sq_q, cnt + 0, gq, betaq, a_lens, LA_, 1, 0, nullptr);
    bn_apply_kernel<<<ROWS_B, 128>>>(Yk, DQK_, sum_k, sq_k, cnt + 1, gk, betak, b_lens, LB_, 1, 0, nullptr);
    bn_apply_kernel<<<ROWS_B, 128>>>(Yv, DV_,  sum_v, sq_v, cnt + 1, gv, betav, b_lens, LB_, 1, 0, nullptr);

    // 3) attention (tensor core)
    attention_tc<<<dim3(S_, LA_ / 64), 512, ATT_SMEM_BYTES>>>(Yq, Yk, Yv, b_lens, Ywv);

    // 4) final projection (fused stats) + BN + ReLU + output mask
    gemm_tc<<<dim3(DQ_ / TBN, ROWS_A / TBM), 256>>>(Ywv, Wf, bf, Yf, ROWS_A, DQ_, DV_,
                                                    a_lens, 7, sum_f, sq_f);
    bn_apply_kernel<<<ROWS_A, 128>>>(Yf, DQ_, sum_f, sq_f, cnt + 0, gf, betaf, a_lens, LA_, 0, 1, out);
}